// round 5
// baseline (speedup 1.0000x reference)
#include <cuda_runtime.h>

#define N_NODES 10000
#define N_EDGES 160000
#define NB 2
#define NT 12
#define NF 16
#define HG 32
#define H 64
#define G 256   /* 4H */
#define NP 4
#define NSEQ 20000
#define NSEQ_PAD 20160
#define BT 24

#define BM 68
#define NTHR 256
#define SP 76    /* div 4 (float4 align); 2*SP mod 32 = 24 -> reduced STS conflicts */
#define K1 96

typedef unsigned long long ull;

__device__ __forceinline__ void fma2(ull& d, ull a, ull b) {
    asm("fma.rn.f32x2 %0, %1, %2, %0;" : "+l"(d) : "l"(a), "l"(b));
}
__device__ __forceinline__ ull dup2(float v) {
    ull r; unsigned u = __float_as_uint(v);
    asm("mov.b64 %0, {%1, %1};" : "=l"(r) : "r"(u));
    return r;
}
__device__ __forceinline__ void unpk(float& lo, float& hi, ull v) {
    unsigned a, b;
    asm("mov.b64 {%0, %1}, %2;" : "=r"(a), "=r"(b) : "l"(v));
    lo = __uint_as_float(a); hi = __uint_as_float(b);
}
__device__ __forceinline__ float tanha(float x) {
    float r; asm("tanh.approx.f32 %0, %1;" : "=f"(r) : "f"(x)); return r;
}
__device__ __forceinline__ float siga(float x) {
    return fmaf(tanha(0.5f * x), 0.5f, 0.5f);
}

// -------- device scratch (zero-initialized; pad region stays zero) --------
__device__ float g_xw[BT * N_NODES * HG];
__device__ float g_seq[NSEQ_PAD * NT * HG];
__device__ float g_w1t[K1 * G];   // [k][g]: rows 0..63 w_hh1^T, 64..95 w_ih1^T
__device__ float g_w2t[H * G];    // [k][g]: w_hh2^T
__device__ int   g_deg[N_NODES];
__device__ int   g_rowptr[N_NODES + 1];
__device__ int   g_cursor[N_NODES];
__device__ int   g_csrc[N_EDGES];
__device__ float g_dinv[N_NODES];

// ---------------- weight transpose prep ----------------
__global__ void k_wprep(const float* __restrict__ w_ih1, const float* __restrict__ w_hh1,
                        const float* __restrict__ w_hh2) {
    int i = blockIdx.x * blockDim.x + threadIdx.x;
    if (i < K1 * G) {
        int k = i >> 8, g = i & 255;
        g_w1t[i] = (k < H) ? w_hh1[g * H + k] : w_ih1[g * HG + (k - H)];
    }
    if (i < H * G) {
        int k = i >> 8, g = i & 255;
        g_w2t[i] = w_hh2[g * H + k];
    }
}

// ---------------- GCN: CSR build ----------------
__global__ void k_initdeg() {
    int i = blockIdx.x * blockDim.x + threadIdx.x;
    if (i < N_NODES) g_deg[i] = 0;
}

__global__ void k_degcount(const int* __restrict__ ei) {
    int e = blockIdx.x * blockDim.x + threadIdx.x;
    if (e < N_EDGES) atomicAdd(&g_deg[ei[N_EDGES + e]], 1);
}

__global__ void k_scan() {
    __shared__ int part[1024];
    const int CH = 10;
    int tid = threadIdx.x;
    int base = tid * CH;
    int loc[CH];
    int s = 0;
#pragma unroll
    for (int j = 0; j < CH; ++j) {
        int idx = base + j;
        int v = (idx < N_NODES) ? g_deg[idx] : 0;
        loc[j] = s; s += v;
    }
    part[tid] = s;
    __syncthreads();
    for (int off = 1; off < 1024; off <<= 1) {
        int v = (tid >= off) ? part[tid - off] : 0;
        __syncthreads();
        part[tid] += v;
        __syncthreads();
    }
    int boff = (tid > 0) ? part[tid - 1] : 0;
#pragma unroll
    for (int j = 0; j < CH; ++j) {
        int idx = base + j;
        if (idx < N_NODES) {
            int rp = boff + loc[j];
            g_rowptr[idx] = rp;
            g_cursor[idx] = rp;
            g_dinv[idx]   = rsqrtf((float)(g_deg[idx] + 1));
        }
    }
    if (tid == 1023) g_rowptr[N_NODES] = part[1023];
}

__global__ void k_fill(const int* __restrict__ ei) {
    int e = blockIdx.x * blockDim.x + threadIdx.x;
    if (e < N_EDGES) {
        int d = ei[N_EDGES + e];
        int p = atomicAdd(&g_cursor[d], 1);
        g_csrc[p] = ei[e];
    }
}

// ---------------- GCN: x @ W ----------------
__global__ void k_xw(const float* __restrict__ x, const float* __restrict__ w) {
    __shared__ float ws[NF * HG];
    for (int i = threadIdx.x; i < NF * HG; i += blockDim.x) ws[i] = w[i];
    __syncthreads();
    int idx = blockIdx.x * blockDim.x + threadIdx.x;
    if (idx >= BT * N_NODES * HG) return;
    int row = idx >> 5;
    int c = idx & 31;
    const float* xr = x + (size_t)row * NF;
    float s = 0.f;
#pragma unroll
    for (int f = 0; f < NF; ++f) s = fmaf(__ldg(&xr[f]), ws[f * HG + c], s);
    g_xw[idx] = s;
}

// ---------------- GCN: per-node gather ----------------
__global__ void k_gather(const float* __restrict__ gcn_b) {
    int gw = (blockIdx.x * blockDim.x + threadIdx.x) >> 5;
    int c = threadIdx.x & 31;
    if (gw >= N_NODES) return;
    int n = gw;
    float dn = g_dinv[n];
    float acc[BT];
#pragma unroll
    for (int bt = 0; bt < BT; ++bt)
        acc[bt] = dn * g_xw[(size_t)(bt * N_NODES + n) * HG + c];
    int e0 = g_rowptr[n], e1 = g_rowptr[n + 1];
    for (int e = e0; e < e1; ++e) {
        int s = g_csrc[e];
        float ds = g_dinv[s];
        const float* xp = g_xw + (size_t)s * HG + c;
#pragma unroll
        for (int bt = 0; bt < BT; ++bt)
            acc[bt] = fmaf(ds, xp[(size_t)bt * N_NODES * HG], acc[bt]);
    }
    float bc = gcn_b[c];
#pragma unroll
    for (int bt = 0; bt < BT; ++bt) {
        int b = bt / NT, t = bt % NT;
        g_seq[((size_t)(b * N_NODES + n) * NT + t) * HG + c] = fmaf(dn, acc[bt], bc);
    }
}

// ---------------- fused LSTM1 + LSTM2 + FC ----------------
// 256 threads / 8 warps per CTA, 2 CTAs per SM. Warp tm owns m in [8tm, 8tm+8);
// warps tm<4 additionally own m_e = 64+tm. Weights streamed from global (L1).
__global__ void __launch_bounds__(NTHR, 2)
k_lstm(const float* __restrict__ zeta,
       const float* __restrict__ b_ih1, const float* __restrict__ b_hh1,
       const float* __restrict__ w_ih2,
       const float* __restrict__ b_ih2, const float* __restrict__ b_hh2,
       const float* __restrict__ fc_w, const float* __restrict__ fc_b,
       float* __restrict__ out) {
    __shared__ float bias1[G], bias2[G], wz[G];
    __shared__ float fcw[512], fcb[8];
    __shared__ float zs[BM * NT];
    __shared__ float y1[NP * BM];
    __shared__ float state[K1 * SP];  // rows 0..63 h (k-major), 64..95 x_t

    int tid = threadIdx.x;
    int tg = tid & 31, tm = tid >> 5;           // tm in [0,8)
    bool xw_extra = (tm < 4);
    int me = 64 + tm;                           // extra m (valid if xw_extra)
    int seq0 = blockIdx.x * BM;

    if (tid < G) {
        bias1[tid] = b_ih1[tid] + b_hh1[tid];
        bias2[tid] = b_ih2[tid] + b_hh2[tid];
        wz[tid]    = w_ih2[tid];
    }
    for (int i = tid; i < 512; i += NTHR) fcw[i] = fc_w[i];
    if (tid < NP) fcb[tid] = fc_b[tid];
    for (int i = tid; i < BM * NT; i += NTHR) {
        int t = i / BM, m = i % BM;
        int seq = seq0 + m;
        float z = 0.f;
        if (seq < NSEQ) {
            int b = seq / N_NODES, n = seq - b * N_NODES;
            z = zeta[(size_t)(b * NT + t) * N_NODES + n];
        }
        zs[m * NT + t] = z;
    }
    for (int i = tid; i < H * SP; i += NTHR) state[i] = 0.f;
    // stage x_0
    for (int i = tid; i < 32 * BM; i += NTHR) {
        int kx = i & 31, m = i >> 5;
        state[(H + kx) * SP + m] = g_seq[(size_t)(seq0 + m) * (NT * HG) + kx];
    }
    __syncthreads();

    float c1[8][2], c1e[2];
#pragma unroll
    for (int im = 0; im < 8; ++im) { c1[im][0] = 0.f; c1[im][1] = 0.f; }
    c1e[0] = 0.f; c1e[1] = 0.f;

    // ======== LSTM 1 (K = 96) ========
    for (int t = 0; t < NT; ++t) {
        ull acc[8][4], acce[4];
        {
            const ull* bp = (const ull*)(bias1 + 2 * tg);
            ull b0 = bp[0], b1 = bp[32], b2 = bp[64], b3 = bp[96];
#pragma unroll
            for (int im = 0; im < 8; ++im) {
                acc[im][0] = b0; acc[im][1] = b1; acc[im][2] = b2; acc[im][3] = b3;
            }
            acce[0] = b0; acce[1] = b1; acce[2] = b2; acce[3] = b3;
        }

#pragma unroll 4
        for (int k = 0; k < K1; ++k) {
            const float* srow = state + k * SP + 8 * tm;
            float4 h0 = *(const float4*)(srow);
            float4 h1 = *(const float4*)(srow + 4);
            const ull* wr = (const ull*)(g_w1t + (k << 8) + 2 * tg);
            ull wa = __ldg(wr), wb = __ldg(wr + 32), wc = __ldg(wr + 64), wd = __ldg(wr + 96);
            float hv[8] = {h0.x, h0.y, h0.z, h0.w, h1.x, h1.y, h1.z, h1.w};
#pragma unroll
            for (int im = 0; im < 8; ++im) {
                ull hd = dup2(hv[im]);
                fma2(acc[im][0], hd, wa);
                fma2(acc[im][1], hd, wb);
                fma2(acc[im][2], hd, wc);
                fma2(acc[im][3], hd, wd);
            }
            if (xw_extra) {
                ull hd = dup2(state[k * SP + me]);
                fma2(acce[0], hd, wa);
                fma2(acce[1], hd, wb);
                fma2(acce[2], hd, wc);
                fma2(acce[3], hd, wd);
            }
        }
        __syncthreads();

        float ho[2][8];
#pragma unroll
        for (int im = 0; im < 8; ++im) {
            float iv[2], fv[2], gv[2], ov[2];
            unpk(iv[0], iv[1], acc[im][0]);
            unpk(fv[0], fv[1], acc[im][1]);
            unpk(gv[0], gv[1], acc[im][2]);
            unpk(ov[0], ov[1], acc[im][3]);
#pragma unroll
            for (int r = 0; r < 2; ++r) {
                float c = fmaf(siga(fv[r]), c1[im][r], siga(iv[r]) * tanha(gv[r]));
                c1[im][r] = c;
                ho[r][im] = siga(ov[r]) * tanha(c);
            }
        }
#pragma unroll
        for (int r = 0; r < 2; ++r) {
            float* dst = state + (2 * tg + r) * SP + 8 * tm;
            *(float4*)dst       = make_float4(ho[r][0], ho[r][1], ho[r][2], ho[r][3]);
            *(float4*)(dst + 4) = make_float4(ho[r][4], ho[r][5], ho[r][6], ho[r][7]);
        }
        if (xw_extra) {
            float iv[2], fv[2], gv[2], ov[2];
            unpk(iv[0], iv[1], acce[0]);
            unpk(fv[0], fv[1], acce[1]);
            unpk(gv[0], gv[1], acce[2]);
            unpk(ov[0], ov[1], acce[3]);
#pragma unroll
            for (int r = 0; r < 2; ++r) {
                float c = fmaf(siga(fv[r]), c1e[r], siga(iv[r]) * tanha(gv[r]));
                c1e[r] = c;
                state[(2 * tg + r) * SP + me] = siga(ov[r]) * tanha(c);
            }
        }
        if (t + 1 < NT) {  // stage x_{t+1} (rows 64..95, not read until after next sync)
            for (int i = tid; i < 32 * BM; i += NTHR) {
                int kx = i & 31, m = i >> 5;
                state[(H + kx) * SP + m] =
                    g_seq[(size_t)(seq0 + m) * (NT * HG) + (t + 1) * HG + kx];
            }
        }
        __syncthreads();
    }

    // ======== FC half 1 (reads final h1) ========
    for (int idx = tid; idx < NP * BM; idx += NTHR) {
        int p = idx / BM, m = idx - p * BM;
        float s = fcb[p];
#pragma unroll 8
        for (int k = 0; k < H; ++k) s = fmaf(state[k * SP + m], fcw[p * 128 + k], s);
        y1[p * BM + m] = s;
    }
    __syncthreads();
    for (int i = tid; i < H * SP; i += NTHR) state[i] = 0.f;
    __syncthreads();

    float c2[8][2], c2e[2];
#pragma unroll
    for (int im = 0; im < 8; ++im) { c2[im][0] = 0.f; c2[im][1] = 0.f; }
    c2e[0] = 0.f; c2e[1] = 0.f;

    // ======== LSTM 2 (K = 64, scalar input folded into init) ========
    for (int t = 0; t < NT; ++t) {
        ull acc[8][4], acce[4];
        {
            const ull* bp = (const ull*)(bias2 + 2 * tg);
            const ull* wp = (const ull*)(wz + 2 * tg);
            ull b0 = bp[0], b1 = bp[32], b2 = bp[64], b3 = bp[96];
            ull z0 = wp[0], z1 = wp[32], z2 = wp[64], z3 = wp[96];
#pragma unroll
            for (int im = 0; im < 8; ++im) {
                ull zd = dup2(zs[(8 * tm + im) * NT + t]);
                acc[im][0] = b0; fma2(acc[im][0], zd, z0);
                acc[im][1] = b1; fma2(acc[im][1], zd, z1);
                acc[im][2] = b2; fma2(acc[im][2], zd, z2);
                acc[im][3] = b3; fma2(acc[im][3], zd, z3);
            }
            ull zd = dup2(xw_extra ? zs[me * NT + t] : 0.f);
            acce[0] = b0; fma2(acce[0], zd, z0);
            acce[1] = b1; fma2(acce[1], zd, z1);
            acce[2] = b2; fma2(acce[2], zd, z2);
            acce[3] = b3; fma2(acce[3], zd, z3);
        }
#pragma unroll 4
        for (int k = 0; k < H; ++k) {
            const float* srow = state + k * SP + 8 * tm;
            float4 h0 = *(const float4*)(srow);
            float4 h1 = *(const float4*)(srow + 4);
            const ull* wr = (const ull*)(g_w2t + (k << 8) + 2 * tg);
            ull wa = __ldg(wr), wb = __ldg(wr + 32), wc = __ldg(wr + 64), wd = __ldg(wr + 96);
            float hv[8] = {h0.x, h0.y, h0.z, h0.w, h1.x, h1.y, h1.z, h1.w};
#pragma unroll
            for (int im = 0; im < 8; ++im) {
                ull hd = dup2(hv[im]);
                fma2(acc[im][0], hd, wa);
                fma2(acc[im][1], hd, wb);
                fma2(acc[im][2], hd, wc);
                fma2(acc[im][3], hd, wd);
            }
            if (xw_extra) {
                ull hd = dup2(state[k * SP + me]);
                fma2(acce[0], hd, wa);
                fma2(acce[1], hd, wb);
                fma2(acce[2], hd, wc);
                fma2(acce[3], hd, wd);
            }
        }
        __syncthreads();

        float ho[2][8];
#pragma unroll
        for (int im = 0; im < 8; ++im) {
            float iv[2], fv[2], gv[2], ov[2];
            unpk(iv[0], iv[1], acc[im][0]);
            unpk(fv[0], fv[1], acc[im][1]);
            unpk(gv[0], gv[1], acc[im][2]);
            unpk(ov[0], ov[1], acc[im][3]);
#pragma unroll
            for (int r = 0; r < 2; ++r) {
                float c = fmaf(siga(fv[r]), c2[im][r], siga(iv[r]) * tanha(gv[r]));
                c2[im][r] = c;
                ho[r][im] = siga(ov[r]) * tanha(c);
            }
        }
#pragma unroll
        for (int r = 0; r < 2; ++r) {
            float* dst = state + (2 * tg + r) * SP + 8 * tm;
            *(float4*)dst       = make_float4(ho[r][0], ho[r][1], ho[r][2], ho[r][3]);
            *(float4*)(dst + 4) = make_float4(ho[r][4], ho[r][5], ho[r][6], ho[r][7]);
        }
        if (xw_extra) {
            float iv[2], fv[2], gv[2], ov[2];
            unpk(iv[0], iv[1], acce[0]);
            unpk(fv[0], fv[1], acce[1]);
            unpk(gv[0], gv[1], acce[2]);
            unpk(ov[0], ov[1], acce[3]);
#pragma unroll
            for (int r = 0; r < 2; ++r) {
                float c = fmaf(siga(fv[r]), c2e[r], siga(iv[r]) * tanha(gv[r]));
                c2e[r] = c;
                state[(2 * tg + r) * SP + me] = siga(ov[r]) * tanha(c);
            }
        }
        __syncthreads();
    }

    // ======== FC half 2 + transposed output write ========
    for (int idx = tid; idx < NP * BM; idx += NTHR) {
        int p = idx / BM, m = idx - p * BM;
        float s = y1[p * BM + m];
#pragma unroll 8
        for (int k = 0; k < H; ++k) s = fmaf(state[k * SP + m], fcw[p * 128 + H + k], s);
        int seq = seq0 + m;
        if (seq < NSEQ) {
            int b = seq / N_NODES, n = seq - b * N_NODES;
            out[(size_t)(b * NP + p) * N_NODES + n] = s;
        }
    }
}

extern "C" void kernel_launch(void* const* d_in, const int* in_sizes, int n_in,
                              void* d_out, int out_size) {
    const float* era5  = (const float*)d_in[0];
    const float* zeta  = (const float*)d_in[1];
    const int*   ei    = (const int*)d_in[2];
    const float* gcn_w = (const float*)d_in[3];
    const float* gcn_b = (const float*)d_in[4];
    const float* w_ih1 = (const float*)d_in[5];
    const float* w_hh1 = (const float*)d_in[6];
    const float* b_ih1 = (const float*)d_in[7];
    const float* b_hh1 = (const float*)d_in[8];
    const float* w_ih2 = (const float*)d_in[9];
    const float* w_hh2 = (const float*)d_in[10];
    const float* b_ih2 = (const float*)d_in[11];
    const float* b_hh2 = (const float*)d_in[12];
    const float* fc_w  = (const float*)d_in[13];
    const float* fc_b  = (const float*)d_in[14];
    float* out = (float*)d_out;

    k_initdeg<<<(N_NODES + 255) / 256, 256>>>();
    k_degcount<<<(N_EDGES + 255) / 256, 256>>>(ei);
    k_wprep<<<(K1 * G + 255) / 256, 256>>>(w_ih1, w_hh1, w_hh2);
    k_scan<<<1, 1024>>>();
    k_fill<<<(N_EDGES + 255) / 256, 256>>>(ei);
    k_xw<<<(BT * N_NODES * HG + 255) / 256, 256>>>(era5, gcn_w);
    k_gather<<<(N_NODES * 32 + 255) / 256, 256>>>(gcn_b);

    k_lstm<<<(NSEQ + BM - 1) / BM, NTHR>>>(
        zeta, b_ih1, b_hh1,
        w_ih2, b_ih2, b_hh2, fc_w, fc_b, out);
}

// round 6
// speedup vs baseline: 1.1020x; 1.1020x over previous
#include <cuda_runtime.h>

#define N_NODES 10000
#define N_EDGES 160000
#define NB 2
#define NT 12
#define NF 16
#define HG 32
#define H 64
#define G 256   /* 4H */
#define NP 4
#define NSEQ 20000
#define NSEQ_PAD 20160
#define BT 24

#define BM 136
#define NTHR 512
#define SP 140   /* div 4 (float4 align); 2*SP mod 32 = 24 -> 2-way STS.128 phases */
#define K1 96
#define SBUF (K1 * SP)

// smem layout (floats)
#define OFF_WBUF  0
#define OFF_B1    24576
#define OFF_B2    24832
#define OFF_WZ    25088
#define OFF_FCW   25344
#define OFF_FCB   25856
#define OFF_ZS    25864            /* 136*12 = 1632 */
#define OFF_Y1    27496            /* 544 */
#define OFF_STATE 28040            /* 2 * 96*140 = 26880 */
#define SMEM_FLOATS (OFF_STATE + 2 * SBUF)   /* 54920 floats = 219.7KB */

typedef unsigned long long ull;

__device__ __forceinline__ void fma2(ull& d, ull a, ull b) {
    asm("fma.rn.f32x2 %0, %1, %2, %0;" : "+l"(d) : "l"(a), "l"(b));
}
__device__ __forceinline__ ull dup2(float v) {
    ull r; unsigned u = __float_as_uint(v);
    asm("mov.b64 %0, {%1, %1};" : "=l"(r) : "r"(u));
    return r;
}
__device__ __forceinline__ void unpk(float& lo, float& hi, ull v) {
    unsigned a, b;
    asm("mov.b64 {%0, %1}, %2;" : "=r"(a), "=r"(b) : "l"(v));
    lo = __uint_as_float(a); hi = __uint_as_float(b);
}
__device__ __forceinline__ float tanha(float x) {
    float r; asm("tanh.approx.f32 %0, %1;" : "=f"(r) : "f"(x)); return r;
}
__device__ __forceinline__ float siga(float x) {
    return fmaf(tanha(0.5f * x), 0.5f, 0.5f);
}

// -------- device scratch (zero-initialized; pad region stays zero) --------
__device__ float g_xw[BT * N_NODES * HG];
__device__ float g_seq[NSEQ_PAD * NT * HG];
__device__ float g_w1t[K1 * G];   // [k][g]: rows 0..63 w_hh1^T, 64..95 w_ih1^T
__device__ float g_w2t[H * G];    // [k][g]: w_hh2^T
__device__ int   g_deg[N_NODES];
__device__ int   g_rowptr[N_NODES + 1];
__device__ int   g_cursor[N_NODES];
__device__ int   g_csrc[N_EDGES];
__device__ float g_dinv[N_NODES];

// ---------------- prep: zero deg + transpose weights ----------------
__global__ void k_prep(const float* __restrict__ w_ih1, const float* __restrict__ w_hh1,
                       const float* __restrict__ w_hh2) {
    int i = blockIdx.x * blockDim.x + threadIdx.x;
    if (i < N_NODES) g_deg[i] = 0;
    if (i < K1 * G) {
        int k = i >> 8, g = i & 255;
        g_w1t[i] = (k < H) ? w_hh1[g * H + k] : w_ih1[g * HG + (k - H)];
    }
    if (i < H * G) {
        int k = i >> 8, g = i & 255;
        g_w2t[i] = w_hh2[g * H + k];
    }
}

// ---------------- fused x@W + degree count ----------------
#define XW_BLOCKS ((BT * N_NODES * HG + 255) / 256)   /* 30000 */
#define DEG_BLOCKS ((N_EDGES + 255) / 256)            /* 625 */

__global__ void k_xwdeg(const float* __restrict__ x, const float* __restrict__ w,
                        const int* __restrict__ ei) {
    if (blockIdx.x < XW_BLOCKS) {
        __shared__ float ws[NF * HG];
        for (int i = threadIdx.x; i < NF * HG; i += blockDim.x) ws[i] = w[i];
        __syncthreads();
        int idx = blockIdx.x * blockDim.x + threadIdx.x;
        if (idx >= BT * N_NODES * HG) return;
        int row = idx >> 5;
        int c = idx & 31;
        const float* xr = x + (size_t)row * NF;
        float s = 0.f;
#pragma unroll
        for (int f = 0; f < NF; ++f) s = fmaf(__ldg(&xr[f]), ws[f * HG + c], s);
        g_xw[idx] = s;
    } else {
        int e = (blockIdx.x - XW_BLOCKS) * blockDim.x + threadIdx.x;
        if (e < N_EDGES) atomicAdd(&g_deg[ei[N_EDGES + e]], 1);
    }
}

// ---------------- scan (shfl-based) ----------------
__global__ void k_scan() {
    __shared__ int woff[32];
    const int CH = 10;
    int tid = threadIdx.x;
    int lane = tid & 31, w = tid >> 5;
    int base = tid * CH;
    int loc[CH];
    int s = 0;
#pragma unroll
    for (int j = 0; j < CH; ++j) {
        int idx = base + j;
        int v = (idx < N_NODES) ? g_deg[idx] : 0;
        loc[j] = s; s += v;
    }
    int inc = s;
#pragma unroll
    for (int off = 1; off < 32; off <<= 1) {
        int n = __shfl_up_sync(0xffffffffu, inc, off);
        if (lane >= off) inc += n;
    }
    if (lane == 31) woff[w] = inc;
    __syncthreads();
    if (w == 0) {
        int v = woff[lane];
        int i2 = v;
#pragma unroll
        for (int off = 1; off < 32; off <<= 1) {
            int n = __shfl_up_sync(0xffffffffu, i2, off);
            if (lane >= off) i2 += n;
        }
        woff[lane] = i2 - v;
    }
    __syncthreads();
    int boff = woff[w] + inc - s;   // exclusive prefix for this thread
#pragma unroll
    for (int j = 0; j < CH; ++j) {
        int idx = base + j;
        if (idx < N_NODES) {
            int rp = boff + loc[j];
            g_rowptr[idx] = rp;
            g_cursor[idx] = rp;
            g_dinv[idx]   = rsqrtf((float)(g_deg[idx] + 1));
        }
    }
    if (tid == 1023) g_rowptr[N_NODES] = boff + s;
}

__global__ void k_fill(const int* __restrict__ ei) {
    int e = blockIdx.x * blockDim.x + threadIdx.x;
    if (e < N_EDGES) {
        int d = ei[N_EDGES + e];
        int p = atomicAdd(&g_cursor[d], 1);
        g_csrc[p] = ei[e];
    }
}

// ---------------- GCN: per-node gather ----------------
__global__ void k_gather(const float* __restrict__ gcn_b) {
    int gw = (blockIdx.x * blockDim.x + threadIdx.x) >> 5;
    int c = threadIdx.x & 31;
    if (gw >= N_NODES) return;
    int n = gw;
    float dn = g_dinv[n];
    float acc[BT];
#pragma unroll
    for (int bt = 0; bt < BT; ++bt)
        acc[bt] = dn * g_xw[(size_t)(bt * N_NODES + n) * HG + c];
    int e0 = g_rowptr[n], e1 = g_rowptr[n + 1];
    for (int e = e0; e < e1; ++e) {
        int s = g_csrc[e];
        float ds = g_dinv[s];
        const float* xp = g_xw + (size_t)s * HG + c;
#pragma unroll
        for (int bt = 0; bt < BT; ++bt)
            acc[bt] = fmaf(ds, xp[(size_t)bt * N_NODES * HG], acc[bt]);
    }
    float bc = gcn_b[c];
#pragma unroll
    for (int bt = 0; bt < BT; ++bt) {
        int b = bt / NT, t = bt % NT;
        g_seq[((size_t)(b * N_NODES + n) * NT + t) * HG + c] = fmaf(dn, acc[bt], bc);
    }
}

// ---------------- fused LSTM1 + LSTM2 + FC ----------------
// 512 threads / 16 warps, 1 CTA/SM, 148 blocks = 1 wave.
// Warp tm owns m in [8tm, 8tm+8); warps tm<8 additionally own m_e = 128+tm.
// Double-buffered state: 1 barrier per timestep.
__global__ void __launch_bounds__(NTHR, 1)
k_lstm(const float* __restrict__ zeta,
       const float* __restrict__ b_ih1, const float* __restrict__ b_hh1,
       const float* __restrict__ w_ih2,
       const float* __restrict__ b_ih2, const float* __restrict__ b_hh2,
       const float* __restrict__ fc_w, const float* __restrict__ fc_b,
       float* __restrict__ out) {
    extern __shared__ float smf[];
    float* wbuf  = smf + OFF_WBUF;
    float* bias1 = smf + OFF_B1;
    float* bias2 = smf + OFF_B2;
    float* wz    = smf + OFF_WZ;
    float* fcw   = smf + OFF_FCW;
    float* fcb   = smf + OFF_FCB;
    float* zs    = smf + OFF_ZS;
    float* y1    = smf + OFF_Y1;
    float* state = smf + OFF_STATE;   // 2 buffers of [96][SP]: rows 0..63 h, 64..95 x_t

    int tid = threadIdx.x;
    int tg = tid & 31, tm = tid >> 5;           // tm in [0,16)
    bool xw_extra = (tm < 8);
    int me = 128 + tm;                          // extra m (valid if xw_extra)
    int seq0 = blockIdx.x * BM;

    // coalesced float4 weight load
    for (int i = 4 * tid; i < K1 * G; i += 4 * NTHR)
        *(float4*)(wbuf + i) = *(const float4*)(g_w1t + i);
    if (tid < G) {
        bias1[tid] = b_ih1[tid] + b_hh1[tid];
        bias2[tid] = b_ih2[tid] + b_hh2[tid];
        wz[tid]    = w_ih2[tid];
    }
    if (tid < 512) fcw[tid] = fc_w[tid];
    if (tid < NP) fcb[tid] = fc_b[tid];
    for (int i = tid; i < BM * NT; i += NTHR) {
        int t = i / BM, m = i % BM;
        int seq = seq0 + m;
        float z = 0.f;
        if (seq < NSEQ) {
            int b = seq / N_NODES, n = seq - b * N_NODES;
            z = zeta[(size_t)(b * NT + t) * N_NODES + n];
        }
        zs[m * NT + t] = z;
    }
    // zero h rows of buf0; stage x_0 into buf0
    for (int i = tid; i < H * SP; i += NTHR) state[i] = 0.f;
    for (int i = tid; i < 32 * BM; i += NTHR) {
        int kx = i & 31, m = i >> 5;
        state[(H + kx) * SP + m] = g_seq[(size_t)(seq0 + m) * (NT * HG) + kx];
    }
    __syncthreads();

    float c1[8][2], c1e[2];
#pragma unroll
    for (int im = 0; im < 8; ++im) { c1[im][0] = 0.f; c1[im][1] = 0.f; }
    c1e[0] = 0.f; c1e[1] = 0.f;

    // ======== LSTM 1 (K = 96) ========
    for (int t = 0; t < NT; ++t) {
        float* sA = state + (t & 1) * SBUF;
        float* sB = state + ((t + 1) & 1) * SBUF;

        ull acc[8][4], acce[4];
        {
            const ull* bp = (const ull*)(bias1 + 2 * tg);
            ull b0 = bp[0], b1 = bp[32], b2 = bp[64], b3 = bp[96];
#pragma unroll
            for (int im = 0; im < 8; ++im) {
                acc[im][0] = b0; acc[im][1] = b1; acc[im][2] = b2; acc[im][3] = b3;
            }
            acce[0] = b0; acce[1] = b1; acce[2] = b2; acce[3] = b3;
        }

#pragma unroll 4
        for (int k = 0; k < K1; ++k) {
            const float* srow = sA + k * SP + 8 * tm;
            float4 h0 = *(const float4*)(srow);
            float4 h1 = *(const float4*)(srow + 4);
            const ull* wr = (const ull*)(wbuf + (k << 8) + 2 * tg);
            ull wa = wr[0], wb = wr[32], wc = wr[64], wd = wr[96];
            float hv[8] = {h0.x, h0.y, h0.z, h0.w, h1.x, h1.y, h1.z, h1.w};
#pragma unroll
            for (int im = 0; im < 8; ++im) {
                ull hd = dup2(hv[im]);
                fma2(acc[im][0], hd, wa);
                fma2(acc[im][1], hd, wb);
                fma2(acc[im][2], hd, wc);
                fma2(acc[im][3], hd, wd);
            }
            if (xw_extra) {
                ull hd = dup2(sA[k * SP + me]);
                fma2(acce[0], hd, wa);
                fma2(acce[1], hd, wb);
                fma2(acce[2], hd, wc);
                fma2(acce[3], hd, wd);
            }
        }

        // activations -> write h_{t+1} into sB (no barrier needed: sA read-only)
        float ho[2][8];
#pragma unroll
        for (int im = 0; im < 8; ++im) {
            float iv[2], fv[2], gv[2], ov[2];
            unpk(iv[0], iv[1], acc[im][0]);
            unpk(fv[0], fv[1], acc[im][1]);
            unpk(gv[0], gv[1], acc[im][2]);
            unpk(ov[0], ov[1], acc[im][3]);
#pragma unroll
            for (int r = 0; r < 2; ++r) {
                float c = fmaf(siga(fv[r]), c1[im][r], siga(iv[r]) * tanha(gv[r]));
                c1[im][r] = c;
                ho[r][im] = siga(ov[r]) * tanha(c);
            }
        }
#pragma unroll
        for (int r = 0; r < 2; ++r) {
            float* dst = sB + (2 * tg + r) * SP + 8 * tm;
            *(float4*)dst       = make_float4(ho[r][0], ho[r][1], ho[r][2], ho[r][3]);
            *(float4*)(dst + 4) = make_float4(ho[r][4], ho[r][5], ho[r][6], ho[r][7]);
        }
        if (xw_extra) {
            float iv[2], fv[2], gv[2], ov[2];
            unpk(iv[0], iv[1], acce[0]);
            unpk(fv[0], fv[1], acce[1]);
            unpk(gv[0], gv[1], acce[2]);
            unpk(ov[0], ov[1], acce[3]);
#pragma unroll
            for (int r = 0; r < 2; ++r) {
                float c = fmaf(siga(fv[r]), c1e[r], siga(iv[r]) * tanha(gv[r]));
                c1e[r] = c;
                sB[(2 * tg + r) * SP + me] = siga(ov[r]) * tanha(c);
            }
        }
        if (t + 1 < NT) {  // stage x_{t+1} into sB
            for (int i = tid; i < 32 * BM; i += NTHR) {
                int kx = i & 31, m = i >> 5;
                sB[(H + kx) * SP + m] =
                    g_seq[(size_t)(seq0 + m) * (NT * HG) + (t + 1) * HG + kx];
            }
        }
        __syncthreads();
    }
    // final h1 lives in buf0 (step 11 wrote buf[(11+1)&1] = buf0)

    // ======== FC half 1 ========
    for (int idx = tid; idx < NP * BM; idx += NTHR) {
        int p = idx / BM, m = idx - p * BM;
        float s = fcb[p];
#pragma unroll 8
        for (int k = 0; k < H; ++k) s = fmaf(state[k * SP + m], fcw[p * 128 + k], s);
        y1[p * BM + m] = s;
    }
    __syncthreads();

    // reload weights (w_hh2^T) and zero buf0 h rows
    for (int i = 4 * tid; i < H * G; i += 4 * NTHR)
        *(float4*)(wbuf + i) = *(const float4*)(g_w2t + i);
    for (int i = tid; i < H * SP; i += NTHR) state[i] = 0.f;
    __syncthreads();

    float c2[8][2], c2e[2];
#pragma unroll
    for (int im = 0; im < 8; ++im) { c2[im][0] = 0.f; c2[im][1] = 0.f; }
    c2e[0] = 0.f; c2e[1] = 0.f;

    // ======== LSTM 2 (K = 64, scalar input folded into init) ========
    for (int t = 0; t < NT; ++t) {
        float* sA = state + (t & 1) * SBUF;
        float* sB = state + ((t + 1) & 1) * SBUF;

        ull acc[8][4], acce[4];
        {
            const ull* bp = (const ull*)(bias2 + 2 * tg);
            const ull* wp = (const ull*)(wz + 2 * tg);
            ull b0 = bp[0], b1 = bp[32], b2 = bp[64], b3 = bp[96];
            ull z0 = wp[0], z1 = wp[32], z2 = wp[64], z3 = wp[96];
#pragma unroll
            for (int im = 0; im < 8; ++im) {
                ull zd = dup2(zs[(8 * tm + im) * NT + t]);
                acc[im][0] = b0; fma2(acc[im][0], zd, z0);
                acc[im][1] = b1; fma2(acc[im][1], zd, z1);
                acc[im][2] = b2; fma2(acc[im][2], zd, z2);
                acc[im][3] = b3; fma2(acc[im][3], zd, z3);
            }
            ull zd = dup2(xw_extra ? zs[me * NT + t] : 0.f);
            acce[0] = b0; fma2(acce[0], zd, z0);
            acce[1] = b1; fma2(acce[1], zd, z1);
            acce[2] = b2; fma2(acce[2], zd, z2);
            acce[3] = b3; fma2(acce[3], zd, z3);
        }
#pragma unroll 4
        for (int k = 0; k < H; ++k) {
            const float* srow = sA + k * SP + 8 * tm;
            float4 h0 = *(const float4*)(srow);
            float4 h1 = *(const float4*)(srow + 4);
            const ull* wr = (const ull*)(wbuf + (k << 8) + 2 * tg);
            ull wa = wr[0], wb = wr[32], wc = wr[64], wd = wr[96];
            float hv[8] = {h0.x, h0.y, h0.z, h0.w, h1.x, h1.y, h1.z, h1.w};
#pragma unroll
            for (int im = 0; im < 8; ++im) {
                ull hd = dup2(hv[im]);
                fma2(acc[im][0], hd, wa);
                fma2(acc[im][1], hd, wb);
                fma2(acc[im][2], hd, wc);
                fma2(acc[im][3], hd, wd);
            }
            if (xw_extra) {
                ull hd = dup2(sA[k * SP + me]);
                fma2(acce[0], hd, wa);
                fma2(acce[1], hd, wb);
                fma2(acce[2], hd, wc);
                fma2(acce[3], hd, wd);
            }
        }

        float ho[2][8];
#pragma unroll
        for (int im = 0; im < 8; ++im) {
            float iv[2], fv[2], gv[2], ov[2];
            unpk(iv[0], iv[1], acc[im][0]);
            unpk(fv[0], fv[1], acc[im][1]);
            unpk(gv[0], gv[1], acc[im][2]);
            unpk(ov[0], ov[1], acc[im][3]);
#pragma unroll
            for (int r = 0; r < 2; ++r) {
                float c = fmaf(siga(fv[r]), c2[im][r], siga(iv[r]) * tanha(gv[r]));
                c2[im][r] = c;
                ho[r][im] = siga(ov[r]) * tanha(c);
            }
        }
#pragma unroll
        for (int r = 0; r < 2; ++r) {
            float* dst = sB + (2 * tg + r) * SP + 8 * tm;
            *(float4*)dst       = make_float4(ho[r][0], ho[r][1], ho[r][2], ho[r][3]);
            *(float4*)(dst + 4) = make_float4(ho[r][4], ho[r][5], ho[r][6], ho[r][7]);
        }
        if (xw_extra) {
            float iv[2], fv[2], gv[2], ov[2];
            unpk(iv[0], iv[1], acce[0]);
            unpk(fv[0], fv[1], acce[1]);
            unpk(gv[0], gv[1], acce[2]);
            unpk(ov[0], ov[1], acce[3]);
#pragma unroll
            for (int r = 0; r < 2; ++r) {
                float c = fmaf(siga(fv[r]), c2e[r], siga(iv[r]) * tanha(gv[r]));
                c2e[r] = c;
                sB[(2 * tg + r) * SP + me] = siga(ov[r]) * tanha(c);
            }
        }
        __syncthreads();
    }
    // final h2 in buf0

    // ======== FC half 2 + transposed output write ========
    for (int idx = tid; idx < NP * BM; idx += NTHR) {
        int p = idx / BM, m = idx - p * BM;
        float s = y1[p * BM + m];
#pragma unroll 8
        for (int k = 0; k < H; ++k) s = fmaf(state[k * SP + m], fcw[p * 128 + H + k], s);
        int seq = seq0 + m;
        if (seq < NSEQ) {
            int b = seq / N_NODES, n = seq - b * N_NODES;
            out[(size_t)(b * NP + p) * N_NODES + n] = s;
        }
    }
}

extern "C" void kernel_launch(void* const* d_in, const int* in_sizes, int n_in,
                              void* d_out, int out_size) {
    const float* era5  = (const float*)d_in[0];
    const float* zeta  = (const float*)d_in[1];
    const int*   ei    = (const int*)d_in[2];
    const float* gcn_w = (const float*)d_in[3];
    const float* gcn_b = (const float*)d_in[4];
    const float* w_ih1 = (const float*)d_in[5];
    const float* w_hh1 = (const float*)d_in[6];
    const float* b_ih1 = (const float*)d_in[7];
    const float* b_hh1 = (const float*)d_in[8];
    const float* w_ih2 = (const float*)d_in[9];
    const float* w_hh2 = (const float*)d_in[10];
    const float* b_ih2 = (const float*)d_in[11];
    const float* b_hh2 = (const float*)d_in[12];
    const float* fc_w  = (const float*)d_in[13];
    const float* fc_b  = (const float*)d_in[14];
    float* out = (float*)d_out;

    k_prep<<<(K1 * G + 255) / 256, 256>>>(w_ih1, w_hh1, w_hh2);
    k_xwdeg<<<XW_BLOCKS + DEG_BLOCKS, 256>>>(era5, gcn_w, ei);
    k_scan<<<1, 1024>>>();
    k_fill<<<(N_EDGES + 255) / 256, 256>>>(ei);
    k_gather<<<(N_NODES * 32 + 255) / 256, 256>>>(gcn_b);

    size_t smem = (size_t)SMEM_FLOATS * sizeof(float);
    cudaFuncSetAttribute(k_lstm, cudaFuncAttributeMaxDynamicSharedMemorySize, (int)smem);
    k_lstm<<<(NSEQ + BM - 1) / BM, NTHR, smem>>>(
        zeta, b_ih1, b_hh1,
        w_ih2, b_ih2, b_hh2, fc_w, fc_b, out);
}

// round 7
// speedup vs baseline: 1.1079x; 1.0053x over previous
#include <cuda_runtime.h>

#define N_NODES 10000
#define N_EDGES 160000
#define NB 2
#define NT 12
#define NF 16
#define HG 32
#define H 64
#define G 256   /* 4H */
#define NP 4
#define NSEQ 20000
#define NSEQ_PAD 20160
#define BT 24

#define BM 136
#define NTHR 512
#define GM 68    /* m per group */
#define SP 136   /* div 4: float4 alignment of state rows */
#define K1 96

// smem layout (floats)
#define OFF_W1    0                 /* 96*256 = 24576 */
#define OFF_W2    24576             /* 64*256 = 16384 */
#define OFF_B1    40960
#define OFF_B2    41216
#define OFF_WZ    41472
#define OFF_FCW   41728             /* 512 */
#define OFF_FCB   42240             /* 8 */
#define OFF_ZS    42248             /* 136*12 = 1632 */
#define OFF_Y1    43880             /* 544 */
#define OFF_STATE 44424             /* 96*136 = 13056 */
#define SMEM_FLOATS (OFF_STATE + K1 * SP)   /* 57480 floats = 229920 B */

typedef unsigned long long ull;

__device__ __forceinline__ void fma2(ull& d, ull a, ull b) {
    asm("fma.rn.f32x2 %0, %1, %2, %0;" : "+l"(d) : "l"(a), "l"(b));
}
__device__ __forceinline__ ull dup2(float v) {
    ull r; unsigned u = __float_as_uint(v);
    asm("mov.b64 %0, {%1, %1};" : "=l"(r) : "r"(u));
    return r;
}
__device__ __forceinline__ void unpk(float& lo, float& hi, ull v) {
    unsigned a, b;
    asm("mov.b64 {%0, %1}, %2;" : "=r"(a), "=r"(b) : "l"(v));
    lo = __uint_as_float(a); hi = __uint_as_float(b);
}
__device__ __forceinline__ float tanha(float x) {
    float r; asm("tanh.approx.f32 %0, %1;" : "=f"(r) : "f"(x)); return r;
}
__device__ __forceinline__ float siga(float x) {
    return fmaf(tanha(0.5f * x), 0.5f, 0.5f);
}
__device__ __forceinline__ void gbar(int id) {
    asm volatile("bar.sync %0, %1;" :: "r"(id), "r"(256) : "memory");
}

// -------- device scratch (zero-initialized; pad region stays zero) --------
__device__ float g_xw[BT * N_NODES * HG];
__device__ float g_seq[NSEQ_PAD * NT * HG];
__device__ float g_w1t[K1 * G];   // [k][g]: rows 0..63 w_hh1^T, 64..95 w_ih1^T
__device__ float g_w2t[H * G];    // [k][g]: w_hh2^T
__device__ int   g_deg[N_NODES];
__device__ int   g_rowptr[N_NODES + 1];
__device__ int   g_cursor[N_NODES];
__device__ int   g_csrc[N_EDGES];
__device__ float g_dinv[N_NODES];

// ---------------- prep: zero deg + transpose weights ----------------
__global__ void k_prep(const float* __restrict__ w_ih1, const float* __restrict__ w_hh1,
                       const float* __restrict__ w_hh2) {
    int i = blockIdx.x * blockDim.x + threadIdx.x;
    if (i < N_NODES) g_deg[i] = 0;
    if (i < K1 * G) {
        int k = i >> 8, g = i & 255;
        g_w1t[i] = (k < H) ? w_hh1[g * H + k] : w_ih1[g * HG + (k - H)];
    }
    if (i < H * G) {
        int k = i >> 8, g = i & 255;
        g_w2t[i] = w_hh2[g * H + k];
    }
}

// ---------------- fused x@W + degree count ----------------
#define XW_BLOCKS ((BT * N_NODES * HG + 255) / 256)   /* 30000 */
#define DEG_BLOCKS ((N_EDGES + 255) / 256)            /* 625 */

__global__ void k_xwdeg(const float* __restrict__ x, const float* __restrict__ w,
                        const int* __restrict__ ei) {
    if (blockIdx.x < XW_BLOCKS) {
        __shared__ float ws[NF * HG];
        for (int i = threadIdx.x; i < NF * HG; i += blockDim.x) ws[i] = w[i];
        __syncthreads();
        int idx = blockIdx.x * blockDim.x + threadIdx.x;
        if (idx >= BT * N_NODES * HG) return;
        int row = idx >> 5;
        int c = idx & 31;
        const float* xr = x + (size_t)row * NF;
        float s = 0.f;
#pragma unroll
        for (int f = 0; f < NF; ++f) s = fmaf(__ldg(&xr[f]), ws[f * HG + c], s);
        g_xw[idx] = s;
    } else {
        int e = (blockIdx.x - XW_BLOCKS) * blockDim.x + threadIdx.x;
        if (e < N_EDGES) atomicAdd(&g_deg[ei[N_EDGES + e]], 1);
    }
}

// ---------------- scan (shfl-based) ----------------
__global__ void k_scan() {
    __shared__ int woff[32];
    const int CH = 10;
    int tid = threadIdx.x;
    int lane = tid & 31, w = tid >> 5;
    int base = tid * CH;
    int loc[CH];
    int s = 0;
#pragma unroll
    for (int j = 0; j < CH; ++j) {
        int idx = base + j;
        int v = (idx < N_NODES) ? g_deg[idx] : 0;
        loc[j] = s; s += v;
    }
    int inc = s;
#pragma unroll
    for (int off = 1; off < 32; off <<= 1) {
        int n = __shfl_up_sync(0xffffffffu, inc, off);
        if (lane >= off) inc += n;
    }
    if (lane == 31) woff[w] = inc;
    __syncthreads();
    if (w == 0) {
        int v = woff[lane];
        int i2 = v;
#pragma unroll
        for (int off = 1; off < 32; off <<= 1) {
            int n = __shfl_up_sync(0xffffffffu, i2, off);
            if (lane >= off) i2 += n;
        }
        woff[lane] = i2 - v;
    }
    __syncthreads();
    int boff = woff[w] + inc - s;
#pragma unroll
    for (int j = 0; j < CH; ++j) {
        int idx = base + j;
        if (idx < N_NODES) {
            int rp = boff + loc[j];
            g_rowptr[idx] = rp;
            g_cursor[idx] = rp;
            g_dinv[idx]   = rsqrtf((float)(g_deg[idx] + 1));
        }
    }
    if (tid == 1023) g_rowptr[N_NODES] = boff + s;
}

__global__ void k_fill(const int* __restrict__ ei) {
    int e = blockIdx.x * blockDim.x + threadIdx.x;
    if (e < N_EDGES) {
        int d = ei[N_EDGES + e];
        int p = atomicAdd(&g_cursor[d], 1);
        g_csrc[p] = ei[e];
    }
}

// ---------------- GCN: per-node gather ----------------
__global__ void k_gather(const float* __restrict__ gcn_b) {
    int gw = (blockIdx.x * blockDim.x + threadIdx.x) >> 5;
    int c = threadIdx.x & 31;
    if (gw >= N_NODES) return;
    int n = gw;
    float dn = g_dinv[n];
    float acc[BT];
#pragma unroll
    for (int bt = 0; bt < BT; ++bt)
        acc[bt] = dn * g_xw[(size_t)(bt * N_NODES + n) * HG + c];
    int e0 = g_rowptr[n], e1 = g_rowptr[n + 1];
    for (int e = e0; e < e1; ++e) {
        int s = g_csrc[e];
        float ds = g_dinv[s];
        const float* xp = g_xw + (size_t)s * HG + c;
#pragma unroll
        for (int bt = 0; bt < BT; ++bt)
            acc[bt] = fmaf(ds, xp[(size_t)bt * N_NODES * HG], acc[bt]);
    }
    float bc = gcn_b[c];
#pragma unroll
    for (int bt = 0; bt < BT; ++bt) {
        int b = bt / NT, t = bt % NT;
        g_seq[((size_t)(b * N_NODES + n) * NT + t) * HG + c] = fmaf(dn, acc[bt], bc);
    }
}

// ---------------- fused LSTM1 + LSTM2 + FC, 2 skewed groups ----------------
// 512 threads = 2 groups of 256. Group gid owns m in [gid*68, gid*68+68).
// Groups synchronize only via their own named barrier -> they drift out of
// phase, so one group's MUFU/store burst overlaps the other's FMA GEMM.
__global__ void __launch_bounds__(NTHR, 1)
k_lstm(const float* __restrict__ zeta,
       const float* __restrict__ b_ih1, const float* __restrict__ b_hh1,
       const float* __restrict__ w_ih2,
       const float* __restrict__ b_ih2, const float* __restrict__ b_hh2,
       const float* __restrict__ fc_w, const float* __restrict__ fc_b,
       float* __restrict__ out) {
    extern __shared__ float smf[];
    float* w1    = smf + OFF_W1;
    float* w2    = smf + OFF_W2;
    float* bias1 = smf + OFF_B1;
    float* bias2 = smf + OFF_B2;
    float* wz    = smf + OFF_WZ;
    float* fcw   = smf + OFF_FCW;
    float* fcb   = smf + OFF_FCB;
    float* zs    = smf + OFF_ZS;
    float* y1    = smf + OFF_Y1;
    float* state = smf + OFF_STATE;   // [96][SP]: rows 0..63 h, 64..95 x_t

    int tid = threadIdx.x;
    int tg = tid & 31;
    int seq0 = blockIdx.x * BM;

    // ---- init (all 512 threads) ----
    for (int i = 4 * tid; i < K1 * G; i += 4 * NTHR)
        *(float4*)(w1 + i) = *(const float4*)(g_w1t + i);
    for (int i = 4 * tid; i < H * G; i += 4 * NTHR)
        *(float4*)(w2 + i) = *(const float4*)(g_w2t + i);
    if (tid < G) {
        bias1[tid] = b_ih1[tid] + b_hh1[tid];
        bias2[tid] = b_ih2[tid] + b_hh2[tid];
        wz[tid]    = w_ih2[tid];
    }
    if (tid < 512) fcw[tid] = fc_w[tid];
    if (tid < NP) fcb[tid] = fc_b[tid];
    for (int i = tid; i < BM * NT; i += NTHR) {
        int t = i / BM, m = i % BM;
        int seq = seq0 + m;
        float z = 0.f;
        if (seq < NSEQ) {
            int b = seq / N_NODES, n = seq - b * N_NODES;
            z = zeta[(size_t)(b * NT + t) * N_NODES + n];
        }
        zs[m * NT + t] = z;
    }
    for (int i = tid; i < H * SP; i += NTHR) state[i] = 0.f;
    for (int i = tid; i < 32 * BM; i += NTHR) {   // stage x_0
        int kx = i & 31, m = i >> 5;
        state[(H + kx) * SP + m] = g_seq[(size_t)(seq0 + m) * (NT * HG) + kx];
    }
    __syncthreads();   // last full-block barrier

    // ---- group setup ----
    int gid = tid >> 8;            // 0 or 1
    int tig = tid & 255;
    int gw  = tig >> 5;            // warp in group, 0..7
    int bar = gid + 1;             // named barrier id
    int mb  = gid * GM + 8 * gw;   // base m (aligned to 4)
    bool xw_extra = (gw < 4);
    int me = gid * GM + 64 + gw;   // extra m (valid if xw_extra)

    float c1[8][2], c1e[2];
#pragma unroll
    for (int im = 0; im < 8; ++im) { c1[im][0] = 0.f; c1[im][1] = 0.f; }
    c1e[0] = 0.f; c1e[1] = 0.f;

    // ======== LSTM 1 (K = 96) ========
    for (int t = 0; t < NT; ++t) {
        ull acc[8][4], acce[4];
        {
            const ull* bp = (const ull*)(bias1 + 2 * tg);
            ull b0 = bp[0], b1 = bp[32], b2 = bp[64], b3 = bp[96];
#pragma unroll
            for (int im = 0; im < 8; ++im) {
                acc[im][0] = b0; acc[im][1] = b1; acc[im][2] = b2; acc[im][3] = b3;
            }
            acce[0] = b0; acce[1] = b1; acce[2] = b2; acce[3] = b3;
        }

#pragma unroll 4
        for (int k = 0; k < K1; ++k) {
            const float* srow = state + k * SP + mb;
            float4 h0 = *(const float4*)(srow);
            float4 h1 = *(const float4*)(srow + 4);
            const ull* wr = (const ull*)(w1 + (k << 8) + 2 * tg);
            ull wa = wr[0], wb = wr[32], wc = wr[64], wd = wr[96];
            float hv[8] = {h0.x, h0.y, h0.z, h0.w, h1.x, h1.y, h1.z, h1.w};
#pragma unroll
            for (int im = 0; im < 8; ++im) {
                ull hd = dup2(hv[im]);
                fma2(acc[im][0], hd, wa);
                fma2(acc[im][1], hd, wb);
                fma2(acc[im][2], hd, wc);
                fma2(acc[im][3], hd, wd);
            }
            if (xw_extra) {
                ull hd = dup2(state[k * SP + me]);
                fma2(acce[0], hd, wa);
                fma2(acce[1], hd, wb);
                fma2(acce[2], hd, wc);
                fma2(acce[3], hd, wd);
            }
        }
        gbar(bar);   // group done reading state

        float ho[2][8];
#pragma unroll
        for (int im = 0; im < 8; ++im) {
            float iv[2], fv[2], gv[2], ov[2];
            unpk(iv[0], iv[1], acc[im][0]);
            unpk(fv[0], fv[1], acc[im][1]);
            unpk(gv[0], gv[1], acc[im][2]);
            unpk(ov[0], ov[1], acc[im][3]);
#pragma unroll
            for (int r = 0; r < 2; ++r) {
                float c = fmaf(siga(fv[r]), c1[im][r], siga(iv[r]) * tanha(gv[r]));
                c1[im][r] = c;
                ho[r][im] = siga(ov[r]) * tanha(c);
            }
        }
#pragma unroll
        for (int r = 0; r < 2; ++r) {
            float* dst = state + (2 * tg + r) * SP + mb;
            *(float4*)dst       = make_float4(ho[r][0], ho[r][1], ho[r][2], ho[r][3]);
            *(float4*)(dst + 4) = make_float4(ho[r][4], ho[r][5], ho[r][6], ho[r][7]);
        }
        if (xw_extra) {
            float iv[2], fv[2], gv[2], ov[2];
            unpk(iv[0], iv[1], acce[0]);
            unpk(fv[0], fv[1], acce[1]);
            unpk(gv[0], gv[1], acce[2]);
            unpk(ov[0], ov[1], acce[3]);
#pragma unroll
            for (int r = 0; r < 2; ++r) {
                float c = fmaf(siga(fv[r]), c1e[r], siga(iv[r]) * tanha(gv[r]));
                c1e[r] = c;
                state[(2 * tg + r) * SP + me] = siga(ov[r]) * tanha(c);
            }
        }
        if (t + 1 < NT) {   // stage x_{t+1} for this group's columns
            for (int i = tig; i < 32 * GM; i += 256) {
                int kx = i & 31, ml = i >> 5;
                int m = gid * GM + ml;
                state[(H + kx) * SP + m] =
                    g_seq[(size_t)(seq0 + m) * (NT * HG) + (t + 1) * HG + kx];
            }
        }
        gbar(bar);   // group writes visible
    }

    // ======== FC half 1 (this group's m columns) ========
    for (int idx = tig; idx < NP * GM; idx += 256) {
        int p = idx / GM, ml = idx - p * GM;
        int m = gid * GM + ml;
        float s = fcb[p];
#pragma unroll 8
        for (int k = 0; k < H; ++k) s = fmaf(state[k * SP + m], fcw[p * 128 + k], s);
        y1[p * BM + m] = s;
    }
    gbar(bar);
    // zero this group's h columns
    for (int i = tig; i < H * GM; i += 256) {
        int k = i / GM, ml = i - k * GM;
        state[k * SP + gid * GM + ml] = 0.f;
    }
    gbar(bar);

    float c2[8][2], c2e[2];
#pragma unroll
    for (int im = 0; im < 8; ++im) { c2[im][0] = 0.f; c2[im][1] = 0.f; }
    c2e[0] = 0.f; c2e[1] = 0.f;

    // ======== LSTM 2 (K = 64, scalar input folded into init) ========
    for (int t = 0; t < NT; ++t) {
        ull acc[8][4], acce[4];
        {
            const ull* bp = (const ull*)(bias2 + 2 * tg);
            const ull* wp = (const ull*)(wz + 2 * tg);
            ull b0 = bp[0], b1 = bp[32], b2 = bp[64], b3 = bp[96];
            ull z0 = wp[0], z1 = wp[32], z2 = wp[64], z3 = wp[96];
#pragma unroll
            for (int im = 0; im < 8; ++im) {
                ull zd = dup2(zs[(mb + im) * NT + t]);
                acc[im][0] = b0; fma2(acc[im][0], zd, z0);
                acc[im][1] = b1; fma2(acc[im][1], zd, z1);
                acc[im][2] = b2; fma2(acc[im][2], zd, z2);
                acc[im][3] = b3; fma2(acc[im][3], zd, z3);
            }
            ull zd = dup2(xw_extra ? zs[me * NT + t] : 0.f);
            acce[0] = b0; fma2(acce[0], zd, z0);
            acce[1] = b1; fma2(acce[1], zd, z1);
            acce[2] = b2; fma2(acce[2], zd, z2);
            acce[3] = b3; fma2(acce[3], zd, z3);
        }
#pragma unroll 4
        for (int k = 0; k < H; ++k) {
            const float* srow = state + k * SP + mb;
            float4 h0 = *(const float4*)(srow);
            float4 h1 = *(const float4*)(srow + 4);
            const ull* wr = (const ull*)(w2 + (k << 8) + 2 * tg);
            ull wa = wr[0], wb = wr[32], wc = wr[64], wd = wr[96];
            float hv[8] = {h0.x, h0.y, h0.z, h0.w, h1.x, h1.y, h1.z, h1.w};
#pragma unroll
            for (int im = 0; im < 8; ++im) {
                ull hd = dup2(hv[im]);
                fma2(acc[im][0], hd, wa);
                fma2(acc[im][1], hd, wb);
                fma2(acc[im][2], hd, wc);
                fma2(acc[im][3], hd, wd);
            }
            if (xw_extra) {
                ull hd = dup2(state[k * SP + me]);
                fma2(acce[0], hd, wa);
                fma2(acce[1], hd, wb);
                fma2(acce[2], hd, wc);
                fma2(acce[3], hd, wd);
            }
        }
        gbar(bar);

        float ho[2][8];
#pragma unroll
        for (int im = 0; im < 8; ++im) {
            float iv[2], fv[2], gv[2], ov[2];
            unpk(iv[0], iv[1], acc[im][0]);
            unpk(fv[0], fv[1], acc[im][1]);
            unpk(gv[0], gv[1], acc[im][2]);
            unpk(ov[0], ov[1], acc[im][3]);
#pragma unroll
            for (int r = 0; r < 2; ++r) {
                float c = fmaf(siga(fv[r]), c2[im][r], siga(iv[r]) * tanha(gv[r]));
                c2[im][r] = c;
                ho[r][im] = siga(ov[r]) * tanha(c);
            }
        }
#pragma unroll
        for (int r = 0; r < 2; ++r) {
            float* dst = state + (2 * tg + r) * SP + mb;
            *(float4*)dst       = make_float4(ho[r][0], ho[r][1], ho[r][2], ho[r][3]);
            *(float4*)(dst + 4) = make_float4(ho[r][4], ho[r][5], ho[r][6], ho[r][7]);
        }
        if (xw_extra) {
            float iv[2], fv[2], gv[2], ov[2];
            unpk(iv[0], iv[1], acce[0]);
            unpk(fv[0], fv[1], acce[1]);
            unpk(gv[0], gv[1], acce[2]);
            unpk(ov[0], ov[1], acce[3]);
#pragma unroll
            for (int r = 0; r < 2; ++r) {
                float c = fmaf(siga(fv[r]), c2e[r], siga(iv[r]) * tanha(gv[r]));
                c2e[r] = c;
                state[(2 * tg + r) * SP + me] = siga(ov[r]) * tanha(c);
            }
        }
        gbar(bar);
    }

    // ======== FC half 2 + transposed output write (group's m columns) ========
    for (int idx = tig; idx < NP * GM; idx += 256) {
        int p = idx / GM, ml = idx - p * GM;
        int m = gid * GM + ml;
        float s = y1[p * BM + m];
#pragma unroll 8
        for (int k = 0; k < H; ++k) s = fmaf(state[k * SP + m], fcw[p * 128 + H + k], s);
        int seq = seq0 + m;
        if (seq < NSEQ) {
            int b = seq / N_NODES, n = seq - b * N_NODES;
            out[(size_t)(b * NP + p) * N_NODES + n] = s;
        }
    }
}

extern "C" void kernel_launch(void* const* d_in, const int* in_sizes, int n_in,
                              void* d_out, int out_size) {
    const float* era5  = (const float*)d_in[0];
    const float* zeta  = (const float*)d_in[1];
    const int*   ei    = (const int*)d_in[2];
    const float* gcn_w = (const float*)d_in[3];
    const float* gcn_b = (const float*)d_in[4];
    const float* w_ih1 = (const float*)d_in[5];
    const float* w_hh1 = (const float*)d_in[6];
    const float* b_ih1 = (const float*)d_in[7];
    const float* b_hh1 = (const float*)d_in[8];
    const float* w_ih2 = (const float*)d_in[9];
    const float* w_hh2 = (const float*)d_in[10];
    const float* b_ih2 = (const float*)d_in[11];
    const float* b_hh2 = (const float*)d_in[12];
    const float* fc_w  = (const float*)d_in[13];
    const float* fc_b  = (const float*)d_in[14];
    float* out = (float*)d_out;

    k_prep<<<(K1 * G + 255) / 256, 256>>>(w_ih1, w_hh1, w_hh2);
    k_xwdeg<<<XW_BLOCKS + DEG_BLOCKS, 256>>>(era5, gcn_w, ei);
    k_scan<<<1, 1024>>>();
    k_fill<<<(N_EDGES + 255) / 256, 256>>>(ei);
    k_gather<<<(N_NODES * 32 + 255) / 256, 256>>>(gcn_b);

    size_t smem = (size_t)SMEM_FLOATS * sizeof(float);
    cudaFuncSetAttribute(k_lstm, cudaFuncAttributeMaxDynamicSharedMemorySize, (int)smem);
    k_lstm<<<(NSEQ + BM - 1) / BM, NTHR, smem>>>(
        zeta, b_ih1, b_hh1,
        w_ih2, b_ih2, b_hh2, fc_w, fc_b, out);
}

// round 8
// speedup vs baseline: 1.1533x; 1.0410x over previous
#include <cuda_runtime.h>

#define N_NODES 10000
#define N_EDGES 160000
#define NB 2
#define NT 12
#define NF 16
#define HG 32
#define H 64
#define G 256   /* 4H */
#define NP 4
#define NSEQ 20000
#define NSEQ_PAD 20160
#define BT 24

#define BM 136
#define NTHR 512
#define GM 68    /* m per group */
#define SP 136   /* div 4: float4 alignment of state rows */
#define K1 96

// smem layout (floats)
#define OFF_W1    0                 /* 96*256 = 24576 */
#define OFF_W2    24576             /* 64*256 = 16384 */
#define OFF_B1    40960
#define OFF_B2    41216
#define OFF_WZ    41472
#define OFF_FCW   41728             /* 512 */
#define OFF_FCB   42240             /* 8 */
#define OFF_ZS    42248             /* 136*12 = 1632 */
#define OFF_Y1    43880             /* 544 */
#define OFF_STATE 44424             /* 96*136 = 13056 */
#define SMEM_FLOATS (OFF_STATE + K1 * SP)   /* 57480 floats = 229920 B */

typedef unsigned long long ull;

__device__ __forceinline__ void fma2(ull& d, ull a, ull b) {
    asm("fma.rn.f32x2 %0, %1, %2, %0;" : "+l"(d) : "l"(a), "l"(b));
}
__device__ __forceinline__ ull dup2(float v) {
    ull r; unsigned u = __float_as_uint(v);
    asm("mov.b64 %0, {%1, %1};" : "=l"(r) : "r"(u));
    return r;
}
__device__ __forceinline__ void unpk(float& lo, float& hi, ull v) {
    unsigned a, b;
    asm("mov.b64 {%0, %1}, %2;" : "=r"(a), "=r"(b) : "l"(v));
    lo = __uint_as_float(a); hi = __uint_as_float(b);
}
__device__ __forceinline__ float tanha(float x) {
    float r; asm("tanh.approx.f32 %0, %1;" : "=f"(r) : "f"(x)); return r;
}
__device__ __forceinline__ float siga(float x) {
    return fmaf(tanha(0.5f * x), 0.5f, 0.5f);
}
__device__ __forceinline__ void gbar(int id) {
    asm volatile("bar.sync %0, %1;" :: "r"(id), "r"(256) : "memory");
}

// -------- device scratch (zero-initialized; pad region stays zero) --------
__device__ float g_aggx[BT * N_NODES * NF];   // [bt][n][f]: dn*(dn*x[n] + sum ds*x[s])
__device__ float g_seq[NSEQ_PAD * NT * HG];
__device__ float g_w1t[K1 * G];
__device__ float g_w2t[H * G];
__device__ int   g_deg[N_NODES];
__device__ int   g_rowptr[N_NODES + 1];
__device__ int   g_cursor[N_NODES];
__device__ int   g_csrc[N_EDGES];
__device__ float g_dinv[N_NODES];

// ---------------- prep: zero deg + transpose weights ----------------
__global__ void k_prep(const float* __restrict__ w_ih1, const float* __restrict__ w_hh1,
                       const float* __restrict__ w_hh2) {
    int i = blockIdx.x * blockDim.x + threadIdx.x;
    if (i < N_NODES) g_deg[i] = 0;
    if (i < K1 * G) {
        int k = i >> 8, g = i & 255;
        g_w1t[i] = (k < H) ? w_hh1[g * H + k] : w_ih1[g * HG + (k - H)];
    }
    if (i < H * G) {
        int k = i >> 8, g = i & 255;
        g_w2t[i] = w_hh2[g * H + k];
    }
}

__global__ void k_deg(const int* __restrict__ ei) {
    int e = blockIdx.x * blockDim.x + threadIdx.x;
    if (e < N_EDGES) atomicAdd(&g_deg[ei[N_EDGES + e]], 1);
}

// ---------------- scan (shfl-based) ----------------
__global__ void k_scan() {
    __shared__ int woff[32];
    const int CH = 10;
    int tid = threadIdx.x;
    int lane = tid & 31, w = tid >> 5;
    int base = tid * CH;
    int loc[CH];
    int s = 0;
#pragma unroll
    for (int j = 0; j < CH; ++j) {
        int idx = base + j;
        int v = (idx < N_NODES) ? g_deg[idx] : 0;
        loc[j] = s; s += v;
    }
    int inc = s;
#pragma unroll
    for (int off = 1; off < 32; off <<= 1) {
        int n = __shfl_up_sync(0xffffffffu, inc, off);
        if (lane >= off) inc += n;
    }
    if (lane == 31) woff[w] = inc;
    __syncthreads();
    if (w == 0) {
        int v = woff[lane];
        int i2 = v;
#pragma unroll
        for (int off = 1; off < 32; off <<= 1) {
            int n = __shfl_up_sync(0xffffffffu, i2, off);
            if (lane >= off) i2 += n;
        }
        woff[lane] = i2 - v;
    }
    __syncthreads();
    int boff = woff[w] + inc - s;
#pragma unroll
    for (int j = 0; j < CH; ++j) {
        int idx = base + j;
        if (idx < N_NODES) {
            int rp = boff + loc[j];
            g_rowptr[idx] = rp;
            g_cursor[idx] = rp;
            g_dinv[idx]   = rsqrtf((float)(g_deg[idx] + 1));
        }
    }
    if (tid == 1023) g_rowptr[N_NODES] = boff + s;
}

__global__ void k_fill(const int* __restrict__ ei) {
    int e = blockIdx.x * blockDim.x + threadIdx.x;
    if (e < N_EDGES) {
        int d = ei[N_EDGES + e];
        int p = atomicAdd(&g_cursor[d], 1);
        g_csrc[p] = ei[e];
    }
}

// ---------------- GCN stage 1: aggregate raw x over in-edges ----------------
// half-warp per node: lane c in [0,16) handles feature c for all 24 (b,t).
__global__ void k_aggx(const float* __restrict__ x) {
    int hw = (blockIdx.x * blockDim.x + threadIdx.x) >> 4;
    int c = threadIdx.x & 15;
    if (hw >= N_NODES) return;
    int n = hw;
    float dn = g_dinv[n];
    float acc[BT];
#pragma unroll
    for (int bt = 0; bt < BT; ++bt)
        acc[bt] = dn * x[(size_t)(bt * N_NODES + n) * NF + c];
    int e0 = g_rowptr[n], e1 = g_rowptr[n + 1];
    for (int e = e0; e < e1; ++e) {
        int s = g_csrc[e];
        float ds = g_dinv[s];
        const float* xp = x + (size_t)s * NF + c;
#pragma unroll
        for (int bt = 0; bt < BT; ++bt)
            acc[bt] = fmaf(ds, xp[(size_t)bt * N_NODES * NF], acc[bt]);
    }
#pragma unroll
    for (int bt = 0; bt < BT; ++bt)
        g_aggx[(size_t)(bt * N_NODES + n) * NF + c] = dn * acc[bt];
}

// ---------------- GCN stage 2: (aggx) @ W + b -> g_seq (seq-major layout) ----------------
__global__ void k_xwseq(const float* __restrict__ w, const float* __restrict__ gcn_b) {
    __shared__ float ws[NF * HG];
    __shared__ float bs[HG];
    for (int i = threadIdx.x; i < NF * HG; i += blockDim.x) ws[i] = w[i];
    if (threadIdx.x < HG) bs[threadIdx.x] = gcn_b[threadIdx.x];
    __syncthreads();
    int idx = blockIdx.x * blockDim.x + threadIdx.x;
    if (idx >= BT * N_NODES * HG) return;
    int row = idx >> 5;          // row = bt*N + n
    int c = idx & 31;
    const float* xr = g_aggx + (size_t)row * NF;
    float s = bs[c];
#pragma unroll
    for (int f = 0; f < NF; ++f) s = fmaf(__ldg(&xr[f]), ws[f * HG + c], s);
    int bt = row / N_NODES, n = row - bt * N_NODES;
    int b = bt / NT, t = bt - b * NT;
    g_seq[((size_t)(b * N_NODES + n) * NT + t) * HG + c] = s;
}

// ---------------- fused LSTM1 + LSTM2 + FC, 2 skewed groups (unchanged R7) ----------------
__global__ void __launch_bounds__(NTHR, 1)
k_lstm(const float* __restrict__ zeta,
       const float* __restrict__ b_ih1, const float* __restrict__ b_hh1,
       const float* __restrict__ w_ih2,
       const float* __restrict__ b_ih2, const float* __restrict__ b_hh2,
       const float* __restrict__ fc_w, const float* __restrict__ fc_b,
       float* __restrict__ out) {
    extern __shared__ float smf[];
    float* w1    = smf + OFF_W1;
    float* w2    = smf + OFF_W2;
    float* bias1 = smf + OFF_B1;
    float* bias2 = smf + OFF_B2;
    float* wz    = smf + OFF_WZ;
    float* fcw   = smf + OFF_FCW;
    float* fcb   = smf + OFF_FCB;
    float* zs    = smf + OFF_ZS;
    float* y1    = smf + OFF_Y1;
    float* state = smf + OFF_STATE;

    int tid = threadIdx.x;
    int tg = tid & 31;
    int seq0 = blockIdx.x * BM;

    for (int i = 4 * tid; i < K1 * G; i += 4 * NTHR)
        *(float4*)(w1 + i) = *(const float4*)(g_w1t + i);
    for (int i = 4 * tid; i < H * G; i += 4 * NTHR)
        *(float4*)(w2 + i) = *(const float4*)(g_w2t + i);
    if (tid < G) {
        bias1[tid] = b_ih1[tid] + b_hh1[tid];
        bias2[tid] = b_ih2[tid] + b_hh2[tid];
        wz[tid]    = w_ih2[tid];
    }
    if (tid < 512) fcw[tid] = fc_w[tid];
    if (tid < NP) fcb[tid] = fc_b[tid];
    for (int i = tid; i < BM * NT; i += NTHR) {
        int t = i / BM, m = i % BM;
        int seq = seq0 + m;
        float z = 0.f;
        if (seq < NSEQ) {
            int b = seq / N_NODES, n = seq - b * N_NODES;
            z = zeta[(size_t)(b * NT + t) * N_NODES + n];
        }
        zs[m * NT + t] = z;
    }
    for (int i = tid; i < H * SP; i += NTHR) state[i] = 0.f;
    for (int i = tid; i < 32 * BM; i += NTHR) {
        int kx = i & 31, m = i >> 5;
        state[(H + kx) * SP + m] = g_seq[(size_t)(seq0 + m) * (NT * HG) + kx];
    }
    __syncthreads();

    int gid = tid >> 8;
    int tig = tid & 255;
    int gw  = tig >> 5;
    int bar = gid + 1;
    int mb  = gid * GM + 8 * gw;
    bool xw_extra = (gw < 4);
    int me = gid * GM + 64 + gw;

    float c1[8][2], c1e[2];
#pragma unroll
    for (int im = 0; im < 8; ++im) { c1[im][0] = 0.f; c1[im][1] = 0.f; }
    c1e[0] = 0.f; c1e[1] = 0.f;

    for (int t = 0; t < NT; ++t) {
        ull acc[8][4], acce[4];
        {
            const ull* bp = (const ull*)(bias1 + 2 * tg);
            ull b0 = bp[0], b1 = bp[32], b2 = bp[64], b3 = bp[96];
#pragma unroll
            for (int im = 0; im < 8; ++im) {
                acc[im][0] = b0; acc[im][1] = b1; acc[im][2] = b2; acc[im][3] = b3;
            }
            acce[0] = b0; acce[1] = b1; acce[2] = b2; acce[3] = b3;
        }

#pragma unroll 4
        for (int k = 0; k < K1; ++k) {
            const float* srow = state + k * SP + mb;
            float4 h0 = *(const float4*)(srow);
            float4 h1 = *(const float4*)(srow + 4);
            const ull* wr = (const ull*)(w1 + (k << 8) + 2 * tg);
            ull wa = wr[0], wb = wr[32], wc = wr[64], wd = wr[96];
            float hv[8] = {h0.x, h0.y, h0.z, h0.w, h1.x, h1.y, h1.z, h1.w};
#pragma unroll
            for (int im = 0; im < 8; ++im) {
                ull hd = dup2(hv[im]);
                fma2(acc[im][0], hd, wa);
                fma2(acc[im][1], hd, wb);
                fma2(acc[im][2], hd, wc);
                fma2(acc[im][3], hd, wd);
            }
            if (xw_extra) {
                ull hd = dup2(state[k * SP + me]);
                fma2(acce[0], hd, wa);
                fma2(acce[1], hd, wb);
                fma2(acce[2], hd, wc);
                fma2(acce[3], hd, wd);
            }
        }
        gbar(bar);

        float ho[2][8];
#pragma unroll
        for (int im = 0; im < 8; ++im) {
            float iv[2], fv[2], gv[2], ov[2];
            unpk(iv[0], iv[1], acc[im][0]);
            unpk(fv[0], fv[1], acc[im][1]);
            unpk(gv[0], gv[1], acc[im][2]);
            unpk(ov[0], ov[1], acc[im][3]);
#pragma unroll
            for (int r = 0; r < 2; ++r) {
                float c = fmaf(siga(fv[r]), c1[im][r], siga(iv[r]) * tanha(gv[r]));
                c1[im][r] = c;
                ho[r][im] = siga(ov[r]) * tanha(c);
            }
        }
#pragma unroll
        for (int r = 0; r < 2; ++r) {
            float* dst = state + (2 * tg + r) * SP + mb;
            *(float4*)dst       = make_float4(ho[r][0], ho[r][1], ho[r][2], ho[r][3]);
            *(float4*)(dst + 4) = make_float4(ho[r][4], ho[r][5], ho[r][6], ho[r][7]);
        }
        if (xw_extra) {
            float iv[2], fv[2], gv[2], ov[2];
            unpk(iv[0], iv[1], acce[0]);
            unpk(fv[0], fv[1], acce[1]);
            unpk(gv[0], gv[1], acce[2]);
            unpk(ov[0], ov[1], acce[3]);
#pragma unroll
            for (int r = 0; r < 2; ++r) {
                float c = fmaf(siga(fv[r]), c1e[r], siga(iv[r]) * tanha(gv[r]));
                c1e[r] = c;
                state[(2 * tg + r) * SP + me] = siga(ov[r]) * tanha(c);
            }
        }
        if (t + 1 < NT) {
            for (int i = tig; i < 32 * GM; i += 256) {
                int kx = i & 31, ml = i >> 5;
                int m = gid * GM + ml;
                state[(H + kx) * SP + m] =
                    g_seq[(size_t)(seq0 + m) * (NT * HG) + (t + 1) * HG + kx];
            }
        }
        gbar(bar);
    }

    for (int idx = tig; idx < NP * GM; idx += 256) {
        int p = idx / GM, ml = idx - p * GM;
        int m = gid * GM + ml;
        float s = fcb[p];
#pragma unroll 8
        for (int k = 0; k < H; ++k) s = fmaf(state[k * SP + m], fcw[p * 128 + k], s);
        y1[p * BM + m] = s;
    }
    gbar(bar);
    for (int i = tig; i < H * GM; i += 256) {
        int k = i / GM, ml = i - k * GM;
        state[k * SP + gid * GM + ml] = 0.f;
    }
    gbar(bar);

    float c2[8][2], c2e[2];
#pragma unroll
    for (int im = 0; im < 8; ++im) { c2[im][0] = 0.f; c2[im][1] = 0.f; }
    c2e[0] = 0.f; c2e[1] = 0.f;

    for (int t = 0; t < NT; ++t) {
        ull acc[8][4], acce[4];
        {
            const ull* bp = (const ull*)(bias2 + 2 * tg);
            const ull* wp = (const ull*)(wz + 2 * tg);
            ull b0 = bp[0], b1 = bp[32], b2 = bp[64], b3 = bp[96];
            ull z0 = wp[0], z1 = wp[32], z2 = wp[64], z3 = wp[96];
#pragma unroll
            for (int im = 0; im < 8; ++im) {
                ull zd = dup2(zs[(mb + im) * NT + t]);
                acc[im][0] = b0; fma2(acc[im][0], zd, z0);
                acc[im][1] = b1; fma2(acc[im][1], zd, z1);
                acc[im][2] = b2; fma2(acc[im][2], zd, z2);
                acc[im][3] = b3; fma2(acc[im][3], zd, z3);
            }
            ull zd = dup2(xw_extra ? zs[me * NT + t] : 0.f);
            acce[0] = b0; fma2(acce[0], zd, z0);
            acce[1] = b1; fma2(acce[1], zd, z1);
            acce[2] = b2; fma2(acce[2], zd, z2);
            acce[3] = b3; fma2(acce[3], zd, z3);
        }
#pragma unroll 4
        for (int k = 0; k < H; ++k) {
            const float* srow = state + k * SP + mb;
            float4 h0 = *(const float4*)(srow);
            float4 h1 = *(const float4*)(srow + 4);
            const ull* wr = (const ull*)(w2 + (k << 8) + 2 * tg);
            ull wa = wr[0], wb = wr[32], wc = wr[64], wd = wr[96];
            float hv[8] = {h0.x, h0.y, h0.z, h0.w, h1.x, h1.y, h1.z, h1.w};
#pragma unroll
            for (int im = 0; im < 8; ++im) {
                ull hd = dup2(hv[im]);
                fma2(acc[im][0], hd, wa);
                fma2(acc[im][1], hd, wb);
                fma2(acc[im][2], hd, wc);
                fma2(acc[im][3], hd, wd);
            }
            if (xw_extra) {
                ull hd = dup2(state[k * SP + me]);
                fma2(acce[0], hd, wa);
                fma2(acce[1], hd, wb);
                fma2(acce[2], hd, wc);
                fma2(acce[3], hd, wd);
            }
        }
        gbar(bar);

        float ho[2][8];
#pragma unroll
        for (int im = 0; im < 8; ++im) {
            float iv[2], fv[2], gv[2], ov[2];
            unpk(iv[0], iv[1], acc[im][0]);
            unpk(fv[0], fv[1], acc[im][1]);
            unpk(gv[0], gv[1], acc[im][2]);
            unpk(ov[0], ov[1], acc[im][3]);
#pragma unroll
            for (int r = 0; r < 2; ++r) {
                float c = fmaf(siga(fv[r]), c2[im][r], siga(iv[r]) * tanha(gv[r]));
                c2[im][r] = c;
                ho[r][im] = siga(ov[r]) * tanha(c);
            }
        }
#pragma unroll
        for (int r = 0; r < 2; ++r) {
            float* dst = state + (2 * tg + r) * SP + mb;
            *(float4*)dst       = make_float4(ho[r][0], ho[r][1], ho[r][2], ho[r][3]);
            *(float4*)(dst + 4) = make_float4(ho[r][4], ho[r][5], ho[r][6], ho[r][7]);
        }
        if (xw_extra) {
            float iv[2], fv[2], gv[2], ov[2];
            unpk(iv[0], iv[1], acce[0]);
            unpk(fv[0], fv[1], acce[1]);
            unpk(gv[0], gv[1], acce[2]);
            unpk(ov[0], ov[1], acce[3]);
#pragma unroll
            for (int r = 0; r < 2; ++r) {
                float c = fmaf(siga(fv[r]), c2e[r], siga(iv[r]) * tanha(gv[r]));
                c2e[r] = c;
                state[(2 * tg + r) * SP + me] = siga(ov[r]) * tanha(c);
            }
        }
        gbar(bar);
    }

    for (int idx = tig; idx < NP * GM; idx += 256) {
        int p = idx / GM, ml = idx - p * GM;
        int m = gid * GM + ml;
        float s = y1[p * BM + m];
#pragma unroll 8
        for (int k = 0; k < H; ++k) s = fmaf(state[k * SP + m], fcw[p * 128 + H + k], s);
        int seq = seq0 + m;
        if (seq < NSEQ) {
            int b = seq / N_NODES, n = seq - b * N_NODES;
            out[(size_t)(b * NP + p) * N_NODES + n] = s;
        }
    }
}

extern "C" void kernel_launch(void* const* d_in, const int* in_sizes, int n_in,
                              void* d_out, int out_size) {
    const float* era5  = (const float*)d_in[0];
    const float* zeta  = (const float*)d_in[1];
    const int*   ei    = (const int*)d_in[2];
    const float* gcn_w = (const float*)d_in[3];
    const float* gcn_b = (const float*)d_in[4];
    const float* w_ih1 = (const float*)d_in[5];
    const float* w_hh1 = (const float*)d_in[6];
    const float* b_ih1 = (const float*)d_in[7];
    const float* b_hh1 = (const float*)d_in[8];
    const float* w_ih2 = (const float*)d_in[9];
    const float* w_hh2 = (const float*)d_in[10];
    const float* b_ih2 = (const float*)d_in[11];
    const float* b_hh2 = (const float*)d_in[12];
    const float* fc_w  = (const float*)d_in[13];
    const float* fc_b  = (const float*)d_in[14];
    float* out = (float*)d_out;

    k_prep<<<(K1 * G + 255) / 256, 256>>>(w_ih1, w_hh1, w_hh2);
    k_deg<<<(N_EDGES + 255) / 256, 256>>>(ei);
    k_scan<<<1, 1024>>>();
    k_fill<<<(N_EDGES + 255) / 256, 256>>>(ei);
    k_aggx<<<(N_NODES * 16 + 255) / 256, 256>>>(era5);
    k_xwseq<<<(BT * N_NODES * HG + 255) / 256, 256>>>(gcn_w, gcn_b);

    size_t smem = (size_t)SMEM_FLOATS * sizeof(float);
    cudaFuncSetAttribute(k_lstm, cudaFuncAttributeMaxDynamicSharedMemorySize, (int)smem);
    k_lstm<<<(NSEQ + BM - 1) / BM, NTHR, smem>>>(
        zeta, b_ih1, b_hh1,
        w_ih2, b_ih2, b_hh2, fc_w, fc_b, out);
}

// round 9
// speedup vs baseline: 1.2598x; 1.0923x over previous
#include <cuda_runtime.h>

#define N_NODES 10000
#define N_EDGES 160000
#define NB 2
#define NT 12
#define NF 16
#define HG 32
#define H 64
#define G 256   /* 4H */
#define NP 4
#define NSEQ 20000
#define NSEQ_PAD 20160
#define BT 24

#define BM 136
#define NTHR 512
#define GM 68    /* m per group */
#define SP 136   /* div 4: float4 alignment of state rows */
#define K1 96

// smem layout (floats)
#define OFF_W1    0                 /* 96*256 = 24576 */
#define OFF_W2    24576             /* 64*256 = 16384 */
#define OFF_B1    40960
#define OFF_B2    41216
#define OFF_WZ    41472
#define OFF_FCW   41728             /* 512 */
#define OFF_FCB   42240             /* 8 */
#define OFF_ZS    42248             /* 136*12 = 1632 */
#define OFF_Y1    43880             /* 544 */
#define OFF_STATE 44424             /* 96*136 = 13056 */
#define SMEM_FLOATS (OFF_STATE + K1 * SP)   /* 57480 floats = 229920 B */

typedef unsigned long long ull;

__device__ __forceinline__ void fma2(ull& d, ull a, ull b) {
    asm("fma.rn.f32x2 %0, %1, %2, %0;" : "+l"(d) : "l"(a), "l"(b));
}
__device__ __forceinline__ ull dup2(float v) {
    ull r; unsigned u = __float_as_uint(v);
    asm("mov.b64 %0, {%1, %1};" : "=l"(r) : "r"(u));
    return r;
}
__device__ __forceinline__ void unpk(float& lo, float& hi, ull v) {
    unsigned a, b;
    asm("mov.b64 {%0, %1}, %2;" : "=r"(a), "=r"(b) : "l"(v));
    lo = __uint_as_float(a); hi = __uint_as_float(b);
}
__device__ __forceinline__ float tanha(float x) {
    float r; asm("tanh.approx.f32 %0, %1;" : "=f"(r) : "f"(x)); return r;
}
__device__ __forceinline__ float siga(float x) {
    return fmaf(tanha(0.5f * x), 0.5f, 0.5f);
}
__device__ __forceinline__ void gbar(int id) {
    asm volatile("bar.sync %0, %1;" :: "r"(id), "r"(256) : "memory");
}

// -------- device scratch (zero-initialized; pad region stays zero) --------
__device__ float g_seq[NSEQ_PAD * NT * HG];
__device__ float g_w1t[K1 * G];
__device__ float g_w2t[H * G];
__device__ int   g_deg[N_NODES];
__device__ int   g_rowptr[N_NODES + 1];
__device__ int   g_cursor[N_NODES];
__device__ int   g_csrc[N_EDGES];
__device__ float g_dinv[N_NODES];

// ---------------- prep: zero deg + transpose weights ----------------
__global__ void k_prep(const float* __restrict__ w_ih1, const float* __restrict__ w_hh1,
                       const float* __restrict__ w_hh2) {
    int i = blockIdx.x * blockDim.x + threadIdx.x;
    if (i < N_NODES) g_deg[i] = 0;
    if (i < K1 * G) {
        int k = i >> 8, g = i & 255;
        g_w1t[i] = (k < H) ? w_hh1[g * H + k] : w_ih1[g * HG + (k - H)];
    }
    if (i < H * G) {
        int k = i >> 8, g = i & 255;
        g_w2t[i] = w_hh2[g * H + k];
    }
}

__global__ void k_deg(const int* __restrict__ ei) {
    int e = blockIdx.x * blockDim.x + threadIdx.x;
    if (e < N_EDGES) atomicAdd(&g_deg[ei[N_EDGES + e]], 1);
}

// ---------------- scan (shfl-based) ----------------
__global__ void k_scan() {
    __shared__ int woff[32];
    const int CH = 10;
    int tid = threadIdx.x;
    int lane = tid & 31, w = tid >> 5;
    int base = tid * CH;
    int loc[CH];
    int s = 0;
#pragma unroll
    for (int j = 0; j < CH; ++j) {
        int idx = base + j;
        int v = (idx < N_NODES) ? g_deg[idx] : 0;
        loc[j] = s; s += v;
    }
    int inc = s;
#pragma unroll
    for (int off = 1; off < 32; off <<= 1) {
        int n = __shfl_up_sync(0xffffffffu, inc, off);
        if (lane >= off) inc += n;
    }
    if (lane == 31) woff[w] = inc;
    __syncthreads();
    if (w == 0) {
        int v = woff[lane];
        int i2 = v;
#pragma unroll
        for (int off = 1; off < 32; off <<= 1) {
            int n = __shfl_up_sync(0xffffffffu, i2, off);
            if (lane >= off) i2 += n;
        }
        woff[lane] = i2 - v;
    }
    __syncthreads();
    int boff = woff[w] + inc - s;
#pragma unroll
    for (int j = 0; j < CH; ++j) {
        int idx = base + j;
        if (idx < N_NODES) {
            int rp = boff + loc[j];
            g_rowptr[idx] = rp;
            g_cursor[idx] = rp;
            g_dinv[idx]   = rsqrtf((float)(g_deg[idx] + 1));
        }
    }
    if (tid == 1023) g_rowptr[N_NODES] = boff + s;
}

__global__ void k_fill(const int* __restrict__ ei) {
    int e = blockIdx.x * blockDim.x + threadIdx.x;
    if (e < N_EDGES) {
        int d = ei[N_EDGES + e];
        int p = atomicAdd(&g_cursor[d], 1);
        g_csrc[p] = ei[e];
    }
}

// ---------------- fused GCN + LSTM1 + LSTM2 + FC ----------------
// Prologue: block-local GCN. One warp per sequence: gather raw x over in-edges
// (lane = (f, t-phase), 6 t's per lane), transpose via per-warp smem tile,
// apply W (per-lane register column), write own g_seq rows (L2-hot reuse).
// Then the R8 LSTM (2 skewed 256-thread groups, named barriers) unchanged.
__global__ void __launch_bounds__(NTHR, 1)
k_lstm(const float* __restrict__ x, const float* __restrict__ gcn_w,
       const float* __restrict__ gcn_b,
       const float* __restrict__ zeta,
       const float* __restrict__ b_ih1, const float* __restrict__ b_hh1,
       const float* __restrict__ w_ih2,
       const float* __restrict__ b_ih2, const float* __restrict__ b_hh2,
       const float* __restrict__ fc_w, const float* __restrict__ fc_b,
       float* __restrict__ out) {
    extern __shared__ float smf[];
    float* w1    = smf + OFF_W1;
    float* w2    = smf + OFF_W2;
    float* bias1 = smf + OFF_B1;
    float* bias2 = smf + OFF_B2;
    float* wz    = smf + OFF_WZ;
    float* fcw   = smf + OFF_FCW;
    float* fcb   = smf + OFF_FCB;
    float* zs    = smf + OFF_ZS;
    float* y1    = smf + OFF_Y1;
    float* state = smf + OFF_STATE;

    int tid = threadIdx.x;
    int tg = tid & 31;
    int seq0 = blockIdx.x * BM;

    // ======== GCN prologue (scratch inside state[]) ========
    {
        float* ws   = state;              // 512
        float* bs   = state + 512;        // 32
        float* aggw = state + 544 + (tid >> 5) * 192;   // per-warp 12*16 tile

        for (int i = tid; i < NF * HG; i += NTHR) ws[i] = gcn_w[i];
        if (tid < HG) bs[tid] = gcn_b[tid];
        __syncthreads();

        int lane = tid & 31;
        int f = lane & 15, t0 = lane >> 4;   // t0 in {0,1}; lane covers t = t0+2*jj
        float wreg[16];
#pragma unroll
        for (int ff = 0; ff < 16; ++ff) wreg[ff] = ws[ff * HG + lane];

        for (int j = tid >> 5; j < BM; j += 16) {
            int seq = seq0 + j;
            if (seq >= NSEQ) break;   // j monotone per warp
            int b = seq / N_NODES, n = seq - b * N_NODES;
            float dn = g_dinv[n];
            const size_t tstride = (size_t)2 * N_NODES * NF;   // t += 2
            const float* xb = x + ((size_t)(b * NT + t0) * N_NODES + n) * NF + f;
            float acc[6];
#pragma unroll
            for (int jj = 0; jj < 6; ++jj) acc[jj] = dn * xb[jj * tstride];
            int e0 = g_rowptr[n], e1 = g_rowptr[n + 1];
            for (int e = e0; e < e1; ++e) {
                int s = g_csrc[e];
                float ds = g_dinv[s];
                const float* xs = x + ((size_t)(b * NT + t0) * N_NODES + s) * NF + f;
#pragma unroll
                for (int jj = 0; jj < 6; ++jj)
                    acc[jj] = fmaf(ds, xs[jj * tstride], acc[jj]);
            }
#pragma unroll
            for (int jj = 0; jj < 6; ++jj)
                aggw[(t0 + 2 * jj) * NF + f] = dn * acc[jj];
            __syncwarp();
            // xw: lane = hg column
            float* gout = g_seq + (size_t)seq * (NT * HG);
            for (int t = 0; t < NT; ++t) {
                float4 a0 = *(const float4*)(aggw + t * NF);
                float4 a1 = *(const float4*)(aggw + t * NF + 4);
                float4 a2 = *(const float4*)(aggw + t * NF + 8);
                float4 a3 = *(const float4*)(aggw + t * NF + 12);
                float s = bs[lane];
                s = fmaf(a0.x, wreg[0], s);  s = fmaf(a0.y, wreg[1], s);
                s = fmaf(a0.z, wreg[2], s);  s = fmaf(a0.w, wreg[3], s);
                s = fmaf(a1.x, wreg[4], s);  s = fmaf(a1.y, wreg[5], s);
                s = fmaf(a1.z, wreg[6], s);  s = fmaf(a1.w, wreg[7], s);
                s = fmaf(a2.x, wreg[8], s);  s = fmaf(a2.y, wreg[9], s);
                s = fmaf(a2.z, wreg[10], s); s = fmaf(a2.w, wreg[11], s);
                s = fmaf(a3.x, wreg[12], s); s = fmaf(a3.y, wreg[13], s);
                s = fmaf(a3.z, wreg[14], s); s = fmaf(a3.w, wreg[15], s);
                gout[t * HG + lane] = s;
            }
            __syncwarp();
        }
    }
    __syncthreads();   // g_seq for this block ready + scratch free

    // ---- init (all 512 threads) ----
    for (int i = 4 * tid; i < K1 * G; i += 4 * NTHR)
        *(float4*)(w1 + i) = *(const float4*)(g_w1t + i);
    for (int i = 4 * tid; i < H * G; i += 4 * NTHR)
        *(float4*)(w2 + i) = *(const float4*)(g_w2t + i);
    if (tid < G) {
        bias1[tid] = b_ih1[tid] + b_hh1[tid];
        bias2[tid] = b_ih2[tid] + b_hh2[tid];
        wz[tid]    = w_ih2[tid];
    }
    if (tid < 512) fcw[tid] = fc_w[tid];
    if (tid < NP) fcb[tid] = fc_b[tid];
    for (int i = tid; i < BM * NT; i += NTHR) {
        int t = i / BM, m = i % BM;
        int seq = seq0 + m;
        float z = 0.f;
        if (seq < NSEQ) {
            int b = seq / N_NODES, n = seq - b * N_NODES;
            z = zeta[(size_t)(b * NT + t) * N_NODES + n];
        }
        zs[m * NT + t] = z;
    }
    __syncthreads();   // scratch reads done before zeroing state
    for (int i = tid; i < H * SP; i += NTHR) state[i] = 0.f;
    for (int i = tid; i < 32 * BM; i += NTHR) {
        int kx = i & 31, m = i >> 5;
        state[(H + kx) * SP + m] = g_seq[(size_t)(seq0 + m) * (NT * HG) + kx];
    }
    __syncthreads();

    int gid = tid >> 8;
    int tig = tid & 255;
    int gw  = tig >> 5;
    int bar = gid + 1;
    int mb  = gid * GM + 8 * gw;
    bool xw_extra = (gw < 4);
    int me = gid * GM + 64 + gw;

    float c1[8][2], c1e[2];
#pragma unroll
    for (int im = 0; im < 8; ++im) { c1[im][0] = 0.f; c1[im][1] = 0.f; }
    c1e[0] = 0.f; c1e[1] = 0.f;

    // ======== LSTM 1 (K = 96) ========
    for (int t = 0; t < NT; ++t) {
        ull acc[8][4], acce[4];
        {
            const ull* bp = (const ull*)(bias1 + 2 * tg);
            ull b0 = bp[0], b1 = bp[32], b2 = bp[64], b3 = bp[96];
#pragma unroll
            for (int im = 0; im < 8; ++im) {
                acc[im][0] = b0; acc[im][1] = b1; acc[im][2] = b2; acc[im][3] = b3;
            }
            acce[0] = b0; acce[1] = b1; acce[2] = b2; acce[3] = b3;
        }

#pragma unroll 4
        for (int k = 0; k < K1; ++k) {
            const float* srow = state + k * SP + mb;
            float4 h0 = *(const float4*)(srow);
            float4 h1 = *(const float4*)(srow + 4);
            const ull* wr = (const ull*)(w1 + (k << 8) + 2 * tg);
            ull wa = wr[0], wb = wr[32], wc = wr[64], wd = wr[96];
            float hv[8] = {h0.x, h0.y, h0.z, h0.w, h1.x, h1.y, h1.z, h1.w};
#pragma unroll
            for (int im = 0; im < 8; ++im) {
                ull hd = dup2(hv[im]);
                fma2(acc[im][0], hd, wa);
                fma2(acc[im][1], hd, wb);
                fma2(acc[im][2], hd, wc);
                fma2(acc[im][3], hd, wd);
            }
            if (xw_extra) {
                ull hd = dup2(state[k * SP + me]);
                fma2(acce[0], hd, wa);
                fma2(acce[1], hd, wb);
                fma2(acce[2], hd, wc);
                fma2(acce[3], hd, wd);
            }
        }
        gbar(bar);

        float ho[2][8];
#pragma unroll
        for (int im = 0; im < 8; ++im) {
            float iv[2], fv[2], gv[2], ov[2];
            unpk(iv[0], iv[1], acc[im][0]);
            unpk(fv[0], fv[1], acc[im][1]);
            unpk(gv[0], gv[1], acc[im][2]);
            unpk(ov[0], ov[1], acc[im][3]);
#pragma unroll
            for (int r = 0; r < 2; ++r) {
                float c = fmaf(siga(fv[r]), c1[im][r], siga(iv[r]) * tanha(gv[r]));
                c1[im][r] = c;
                ho[r][im] = siga(ov[r]) * tanha(c);
            }
        }
#pragma unroll
        for (int r = 0; r < 2; ++r) {
            float* dst = state + (2 * tg + r) * SP + mb;
            *(float4*)dst       = make_float4(ho[r][0], ho[r][1], ho[r][2], ho[r][3]);
            *(float4*)(dst + 4) = make_float4(ho[r][4], ho[r][5], ho[r][6], ho[r][7]);
        }
        if (xw_extra) {
            float iv[2], fv[2], gv[2], ov[2];
            unpk(iv[0], iv[1], acce[0]);
            unpk(fv[0], fv[1], acce[1]);
            unpk(gv[0], gv[1], acce[2]);
            unpk(ov[0], ov[1], acce[3]);
#pragma unroll
            for (int r = 0; r < 2; ++r) {
                float c = fmaf(siga(fv[r]), c1e[r], siga(iv[r]) * tanha(gv[r]));
                c1e[r] = c;
                state[(2 * tg + r) * SP + me] = siga(ov[r]) * tanha(c);
            }
        }
        if (t + 1 < NT) {
            for (int i = tig; i < 32 * GM; i += 256) {
                int kx = i & 31, ml = i >> 5;
                int m = gid * GM + ml;
                state[(H + kx) * SP + m] =
                    g_seq[(size_t)(seq0 + m) * (NT * HG) + (t + 1) * HG + kx];
            }
        }
        gbar(bar);
    }

    for (int idx = tig; idx < NP * GM; idx += 256) {
        int p = idx / GM, ml = idx - p * GM;
        int m = gid * GM + ml;
        float s = fcb[p];
#pragma unroll 8
        for (int k = 0; k < H; ++k) s = fmaf(state[k * SP + m], fcw[p * 128 + k], s);
        y1[p * BM + m] = s;
    }
    gbar(bar);
    for (int i = tig; i < H * GM; i += 256) {
        int k = i / GM, ml = i - k * GM;
        state[k * SP + gid * GM + ml] = 0.f;
    }
    gbar(bar);

    float c2[8][2], c2e[2];
#pragma unroll
    for (int im = 0; im < 8; ++im) { c2[im][0] = 0.f; c2[im][1] = 0.f; }
    c2e[0] = 0.f; c2e[1] = 0.f;

    // ======== LSTM 2 (K = 64, scalar input folded into init) ========
    for (int t = 0; t < NT; ++t) {
        ull acc[8][4], acce[4];
        {
            const ull* bp = (const ull*)(bias2 + 2 * tg);
            const ull* wp = (const ull*)(wz + 2 * tg);
            ull b0 = bp[0], b1 = bp[32], b2 = bp[64], b3 = bp[96];
            ull z0 = wp[0], z1 = wp[32], z2 = wp[64], z3 = wp[96];
#pragma unroll
            for (int im = 0; im < 8; ++im) {
                ull zd = dup2(zs[(mb + im) * NT + t]);
                acc[im][0] = b0; fma2(acc[im][0], zd, z0);
                acc[im][1] = b1; fma2(acc[im][1], zd, z1);
                acc[im][2] = b2; fma2(acc[im][2], zd, z2);
                acc[im][3] = b3; fma2(acc[im][3], zd, z3);
            }
            ull zd = dup2(xw_extra ? zs[me * NT + t] : 0.f);
            acce[0] = b0; fma2(acce[0], zd, z0);
            acce[1] = b1; fma2(acce[1], zd, z1);
            acce[2] = b2; fma2(acce[2], zd, z2);
            acce[3] = b3; fma2(acce[3], zd, z3);
        }
#pragma unroll 4
        for (int k = 0; k < H; ++k) {
            const float* srow = state + k * SP + mb;
            float4 h0 = *(const float4*)(srow);
            float4 h1 = *(const float4*)(srow + 4);
            const ull* wr = (const ull*)(w2 + (k << 8) + 2 * tg);
            ull wa = wr[0], wb = wr[32], wc = wr[64], wd = wr[96];
            float hv[8] = {h0.x, h0.y, h0.z, h0.w, h1.x, h1.y, h1.z, h1.w};
#pragma unroll
            for (int im = 0; im < 8; ++im) {
                ull hd = dup2(hv[im]);
                fma2(acc[im][0], hd, wa);
                fma2(acc[im][1], hd, wb);
                fma2(acc[im][2], hd, wc);
                fma2(acc[im][3], hd, wd);
            }
            if (xw_extra) {
                ull hd = dup2(state[k * SP + me]);
                fma2(acce[0], hd, wa);
                fma2(acce[1], hd, wb);
                fma2(acce[2], hd, wc);
                fma2(acce[3], hd, wd);
            }
        }
        gbar(bar);

        float ho[2][8];
#pragma unroll
        for (int im = 0; im < 8; ++im) {
            float iv[2], fv[2], gv[2], ov[2];
            unpk(iv[0], iv[1], acc[im][0]);
            unpk(fv[0], fv[1], acc[im][1]);
            unpk(gv[0], gv[1], acc[im][2]);
            unpk(ov[0], ov[1], acc[im][3]);
#pragma unroll
            for (int r = 0; r < 2; ++r) {
                float c = fmaf(siga(fv[r]), c2[im][r], siga(iv[r]) * tanha(gv[r]));
                c2[im][r] = c;
                ho[r][im] = siga(ov[r]) * tanha(c);
            }
        }
#pragma unroll
        for (int r = 0; r < 2; ++r) {
            float* dst = state + (2 * tg + r) * SP + mb;
            *(float4*)dst       = make_float4(ho[r][0], ho[r][1], ho[r][2], ho[r][3]);
            *(float4*)(dst + 4) = make_float4(ho[r][4], ho[r][5], ho[r][6], ho[r][7]);
        }
        if (xw_extra) {
            float iv[2], fv[2], gv[2], ov[2];
            unpk(iv[0], iv[1], acce[0]);
            unpk(fv[0], fv[1], acce[1]);
            unpk(gv[0], gv[1], acce[2]);
            unpk(ov[0], ov[1], acce[3]);
#pragma unroll
            for (int r = 0; r < 2; ++r) {
                float c = fmaf(siga(fv[r]), c2e[r], siga(iv[r]) * tanha(gv[r]));
                c2e[r] = c;
                state[(2 * tg + r) * SP + me] = siga(ov[r]) * tanha(c);
            }
        }
        gbar(bar);
    }

    for (int idx = tig; idx < NP * GM; idx += 256) {
        int p = idx / GM, ml = idx - p * GM;
        int m = gid * GM + ml;
        float s = y1[p * BM + m];
#pragma unroll 8
        for (int k = 0; k < H; ++k) s = fmaf(state[k * SP + m], fcw[p * 128 + H + k], s);
        int seq = seq0 + m;
        if (seq < NSEQ) {
            int b = seq / N_NODES, n = seq - b * N_NODES;
            out[(size_t)(b * NP + p) * N_NODES + n] = s;
        }
    }
}

extern "C" void kernel_launch(void* const* d_in, const int* in_sizes, int n_in,
                              void* d_out, int out_size) {
    const float* era5  = (const float*)d_in[0];
    const float* zeta  = (const float*)d_in[1];
    const int*   ei    = (const int*)d_in[2];
    const float* gcn_w = (const float*)d_in[3];
    const float* gcn_b = (const float*)d_in[4];
    const float* w_ih1 = (const float*)d_in[5];
    const float* w_hh1 = (const float*)d_in[6];
    const float* b_ih1 = (const float*)d_in[7];
    const float* b_hh1 = (const float*)d_in[8];
    const float* w_ih2 = (const float*)d_in[9];
    const float* w_hh2 = (const float*)d_in[10];
    const float* b_ih2 = (const float*)d_in[11];
    const float* b_hh2 = (const float*)d_in[12];
    const float* fc_w  = (const float*)d_in[13];
    const float* fc_b  = (const float*)d_in[14];
    float* out = (float*)d_out;

    k_prep<<<(K1 * G + 255) / 256, 256>>>(w_ih1, w_hh1, w_hh2);
    k_deg<<<(N_EDGES + 255) / 256, 256>>>(ei);
    k_scan<<<1, 1024>>>();
    k_fill<<<(N_EDGES + 255) / 256, 256>>>(ei);

    size_t smem = (size_t)SMEM_FLOATS * sizeof(float);
    cudaFuncSetAttribute(k_lstm, cudaFuncAttributeMaxDynamicSharedMemorySize, (int)smem);
    k_lstm<<<(NSEQ + BM - 1) / BM, NTHR, smem>>>(
        era5, gcn_w, gcn_b,
        zeta, b_ih1, b_hh1,
        w_ih2, b_ih2, b_hh2, fc_w, fc_b, out);
}